// round 4
// baseline (speedup 1.0000x reference)
#include <cuda_runtime.h>
#include <math.h>

// ----- problem constants -----
#define BB    2
#define AA    900
#define EDD   256
#define NGRP  8
#define NCAM  6
#define NLVL  4
#define NPT   7
#define NW    1344            // NGRP*NCAM*NLVL*NPT
#define NBA   (BB*AA)         // 1800
#define NDESC (NCAM*NPT*NLVL) // 168
#define NBC   (BB*NCAM)       // 12

// level geometry
#define HW0 11264
#define HW1 2816
#define HW2 704
#define HW3 176
// pixel bases in the unified NHWC buffer
#define PB0 0
#define PB1 (NBC*HW0)                  // 135168
#define PB2 (PB1 + NBC*HW1)            // 168960
#define PB3 (PB2 + NBC*HW2)            // 177408
#define NPIX (PB3 + NBC*HW3)           // 179520

// conversion tile blocks per level: NBC * ceil(HW/32) * 8
#define CV0 (NBC*352*8)   // 33792
#define CV1 (NBC*88*8)    // 8448
#define CV2 (NBC*22*8)    // 2112
#define CV3 (NBC*6*8)     // 576
#define CVTOT (CV0+CV1+CV2+CV3)  // 44928

#define GEMM_BLKS ((NW/64) * ((NBA+127)/128))   // 21*15 = 315

// ----- scratch (allocation-free: device globals) -----
__device__ float g_featT[EDD * NBA];   // (inst+emb)^T   [256][1800]
__device__ float g_wfcT[EDD * NW];     // w_fc^T         [256][1344]
__device__ float g_woutT[EDD * EDD];   // w_out^T        [256][256]
__device__ float g_w[NBA * NW];        // fc logits      [1800][1344]
__device__ float g_fusedT[EDD * NBA];  // fused features^T [256][1800]
__device__ float g_nhwc[(size_t)NPIX * EDD];  // unified NHWC features (~184MB)

// =====================================================================
// Prep: three transposes merged.  block (32,8).
//   range 0: featT = (inst+emb)^T   (8 x 57  = 456 blocks)
//   range 1: wfcT  = w_fc^T         (8 x 42  = 336 blocks)
//   range 2: woutT = w_out^T        (8 x 8   = 64  blocks)
// =====================================================================
__device__ __forceinline__ void do_transpose(
    const float* in, const float* in2, float* out, int M,
    int bx, int by, bool add2)
{
    __shared__ float t[32][33];
    const int k0 = bx * 32;
    const int m0 = by * 32;
    const int tx = threadIdx.x, ty = threadIdx.y;
#pragma unroll
    for (int j = ty; j < 32; j += 8) {
        int m = m0 + j;
        float v = 0.f;
        if (m < M) {
            v = in[(size_t)m * 256 + k0 + tx];
            if (add2) v += in2[(size_t)m * 256 + k0 + tx];
        }
        t[j][tx] = v;
    }
    __syncthreads();
#pragma unroll
    for (int j = ty; j < 32; j += 8) {
        int m = m0 + tx;
        if (m < M) out[(size_t)(k0 + j) * M + m] = t[tx][j];
    }
}

__global__ void __launch_bounds__(256) prep_kernel(
    const float* __restrict__ inst, const float* __restrict__ emb,
    const float* __restrict__ w_fc, const float* __restrict__ w_out,
    float* __restrict__ featT, float* __restrict__ wfcT, float* __restrict__ woutT)
{
    int bid = blockIdx.x;
    if (bid < 456) {
        do_transpose(inst, emb, featT, NBA, bid % 8, bid / 8, true);
    } else if (bid < 456 + 336) {
        bid -= 456;
        do_transpose(w_fc, 0, wfcT, NW, bid % 8, bid / 8, false);
    } else {
        bid -= 456 + 336;
        do_transpose(w_out, 0, woutT, EDD, bid % 8, bid / 8, false);
    }
}

// =====================================================================
// Mega kernel: blocks [0, GEMM_BLKS) do the FC GEMM (compute-bound),
// blocks [GEMM_BLKS, GEMM_BLKS+CVTOT) do NCHW->NHWC conversion
// (DRAM-bound).  The two overlap across SMs in one launch.
// 128 threads per block.
// =====================================================================
__global__ void __launch_bounds__(128) mega_kernel(
    const float* __restrict__ AT, const float* __restrict__ BT,
    const float* __restrict__ bias, float* __restrict__ C,
    const float* __restrict__ f0, const float* __restrict__ f1,
    const float* __restrict__ f2, const float* __restrict__ f3)
{
    __shared__ float sm[6144];   // GEMM: As 32x128 (4096) + Bs 32x64 (2048); conv: 32x33
    const int tid = threadIdx.x;

    if (blockIdx.x < GEMM_BLKS) {
        // ---------------- FC GEMM: C[1800][1344] = AT^T @ BT + bias ----
        const int gx = blockIdx.x % (NW / 64);
        const int gy = blockIdx.x / (NW / 64);
        const int bm0 = gy * 128;
        const int bn0 = gx * 64;
        const int w    = tid >> 5;
        const int lane = tid & 31;
        const int ry   = lane >> 3;
        const int rx   = lane & 7;
        const int m0   = w * 32 + ry * 8;
        const int n0   = rx * 8;
        const int M = NBA, N = NW;

        float acc[8][8];
#pragma unroll
        for (int i = 0; i < 8; i++)
#pragma unroll
            for (int j = 0; j < 8; j++) acc[i][j] = 0.f;

        for (int kt = 0; kt < 256; kt += 32) {
#pragma unroll
            for (int s = 0; s < 8; s++) {
                int id = tid + s * 128;
                int k = id >> 5, mq = id & 31;
                int m = bm0 + mq * 4;
                float4 v = make_float4(0.f, 0.f, 0.f, 0.f);
                if (m < M) v = *(const float4*)(AT + (size_t)(kt + k) * M + m);
                *(float4*)&sm[k * 128 + mq * 4] = v;
            }
#pragma unroll
            for (int s = 0; s < 4; s++) {
                int id = tid + s * 128;
                int k = id >> 4, nq = id & 15;
                *(float4*)&sm[4096 + k * 64 + nq * 4] =
                    *(const float4*)(BT + (size_t)(kt + k) * N + bn0 + nq * 4);
            }
            __syncthreads();

#pragma unroll
            for (int k = 0; k < 32; k++) {
                float4 a0 = *(const float4*)&sm[k * 128 + m0];
                float4 a1 = *(const float4*)&sm[k * 128 + m0 + 4];
                float4 b0 = *(const float4*)&sm[4096 + k * 64 + n0];
                float4 b1 = *(const float4*)&sm[4096 + k * 64 + n0 + 4];
                float am[8] = {a0.x, a0.y, a0.z, a0.w, a1.x, a1.y, a1.z, a1.w};
                float bv[8] = {b0.x, b0.y, b0.z, b0.w, b1.x, b1.y, b1.z, b1.w};
#pragma unroll
                for (int i = 0; i < 8; i++)
#pragma unroll
                    for (int j = 0; j < 8; j++)
                        acc[i][j] = fmaf(am[i], bv[j], acc[i][j]);
            }
            __syncthreads();
        }

        float4 bb0 = *(const float4*)(bias + bn0 + n0);
        float4 bb1 = *(const float4*)(bias + bn0 + n0 + 4);
        float bv[8] = {bb0.x, bb0.y, bb0.z, bb0.w, bb1.x, bb1.y, bb1.z, bb1.w};
#pragma unroll
        for (int i = 0; i < 8; i++) {
            int m = bm0 + m0 + i;
            if (m >= M) continue;
            float4 o0, o1;
            o0.x = acc[i][0] + bv[0]; o0.y = acc[i][1] + bv[1];
            o0.z = acc[i][2] + bv[2]; o0.w = acc[i][3] + bv[3];
            o1.x = acc[i][4] + bv[4]; o1.y = acc[i][5] + bv[5];
            o1.z = acc[i][6] + bv[6]; o1.w = acc[i][7] + bv[7];
            *(float4*)(C + (size_t)m * N + bn0 + n0)     = o0;
            *(float4*)(C + (size_t)m * N + bn0 + n0 + 4) = o1;
        }
    } else {
        // ---------------- NCHW -> NHWC conversion ----------------------
        int cb = blockIdx.x - GEMM_BLKS;
        const float* fin; int HWl, tilesHW, pbase;
        if (cb < CV0)               { fin = f0; HWl = HW0; tilesHW = 352; pbase = PB0; }
        else if ((cb -= CV0) < CV1) { fin = f1; HWl = HW1; tilesHW = 88;  pbase = PB1; }
        else if ((cb -= CV1) < CV2) { fin = f2; HWl = HW2; tilesHW = 22;  pbase = PB2; }
        else       { cb -= CV2;       fin = f3; HWl = HW3; tilesHW = 6;   pbase = PB3; }
        const int nt = tilesHW * 8;
        const int bc  = cb / nt;
        const int r   = cb % nt;
        const int hw0 = (r >> 3) * 32;
        const int c0  = (r & 7) * 32;
        float (*t)[33] = (float(*)[33])sm;
        const int tx = tid & 31, ty = tid >> 5;   // 32 x 4

        const float* ip = fin + (size_t)bc * 256 * HWl;
#pragma unroll
        for (int j = ty; j < 32; j += 4) {
            int hw = hw0 + tx;
            t[j][tx] = (hw < HWl) ? ip[(size_t)(c0 + j) * HWl + hw] : 0.f;
        }
        __syncthreads();
        float* op = g_nhwc + ((size_t)(pbase + bc * HWl)) * 256;
#pragma unroll
        for (int j = ty; j < 32; j += 4) {
            int hw = hw0 + j;
            if (hw < HWl) op[(size_t)hw * 256 + c0 + tx] = t[tx][j];
        }
    }
}

// =====================================================================
// Fused aggregation (NHWC gathers): softmax + keypoint projection +
// compacted descriptors + coalesced gather/fuse.
// One block per anchor, 256 threads (one channel each).
// =====================================================================
__global__ void __launch_bounds__(256) agg_kernel(
    const float* __restrict__ anchor, const float* __restrict__ proj,
    const float* __restrict__ wh)
{
    __shared__ float  s_w[NW];
    __shared__ float  s_uv[NCAM * NPT][2];
    __shared__ int4   s_dA[NDESC];   // {pix00, dxOff(floats), dyOff(floats), widx}
    __shared__ float4 s_dW[NDESC];   // bilinear corner weights
    __shared__ int    s_wcnt[8];

    const int ba   = blockIdx.x;
    const int b    = ba / AA;
    const int tid  = threadIdx.x;
    const int c    = tid;
    const int wrp  = tid >> 5;
    const int lane = tid & 31;

    for (int i = tid; i < NW; i += 256) s_w[i] = g_w[(size_t)ba * NW + i];

    if (tid < NCAM * NPT) {
        const float fsx[7] = {0.f, 0.45f, -0.45f, 0.f, 0.f, 0.f, 0.f};
        const float fsy[7] = {0.f, 0.f, 0.f, 0.45f, -0.45f, 0.f, 0.f};
        const float fsz[7] = {0.f, 0.f, 0.f, 0.f, 0.f, 0.45f, -0.45f};
        int cam = tid / NPT, p = tid % NPT;
        const float* an = anchor + (size_t)ba * 8;
        float e0 = expf(an[3]), e1 = expf(an[4]), e2 = expf(an[5]);
        float k0 = fsx[p] * e0, k1 = fsy[p] * e1, k2 = fsz[p] * e2;
        float sn = an[6], cs = an[7];
        float X = cs * k0 - sn * k1 + an[0];
        float Y = sn * k0 + cs * k1 + an[1];
        float Z = k2 + an[2];
        const float* M = proj + (size_t)(b * NCAM + cam) * 16;
        float d0 = M[0] * X + M[1] * Y + M[2]  * Z + M[3];
        float d1 = M[4] * X + M[5] * Y + M[6]  * Z + M[7];
        float d2 = M[8] * X + M[9] * Y + M[10] * Z + M[11];
        float iz = 1.f / fmaxf(d2, 1e-5f);
        float x = d0 * iz / fmaxf(wh[(size_t)(b * NCAM + cam) * 2 + 0], 1e-5f);
        float y = d1 * iz / fmaxf(wh[(size_t)(b * NCAM + cam) * 2 + 1], 1e-5f);
        s_uv[tid][0] = x * 2.f - 1.f;
        s_uv[tid][1] = y * 2.f - 1.f;
    }
    __syncthreads();

    // softmax over 168 entries, group = warp id
    {
        float mx = -INFINITY;
        for (int cc = lane; cc < 168; cc += 32) mx = fmaxf(mx, s_w[cc * 8 + wrp]);
#pragma unroll
        for (int o = 16; o; o >>= 1) mx = fmaxf(mx, __shfl_xor_sync(0xffffffffu, mx, o));
        float sum = 0.f;
        for (int cc = lane; cc < 168; cc += 32) {
            float e = expf(s_w[cc * 8 + wrp] - mx);
            s_w[cc * 8 + wrp] = e;
            sum += e;
        }
#pragma unroll
        for (int o = 16; o; o >>= 1) sum += __shfl_xor_sync(0xffffffffu, sum, o);
        float inv = 1.f / sum;
        for (int cc = lane; cc < 168; cc += 32) s_w[cc * 8 + wrp] *= inv;
    }

    // descriptor precompute (NHWC pixel offsets)
    const int Hl[4]  = {64, 32, 16, 8};
    const int Wl[4]  = {176, 88, 44, 22};
    const int HWl[4] = {HW0, HW1, HW2, HW3};
    const int PBl[4] = {PB0, PB1, PB2, PB3};
    int flag = 0;
    int4 dA; float4 dW;
    if (tid < NDESC) {
        int d = tid;
        int cam = d / (NPT * NLVL);
        int r   = d - cam * (NPT * NLVL);
        int p   = r >> 2;
        int lvl = r & 3;
        float u = s_uv[cam * NPT + p][0];
        float v = s_uv[cam * NPT + p][1];
        const int H = Hl[lvl], W = Wl[lvl];
        float gx = (u + 1.f) * (W * 0.5f) - 0.5f;
        float gy = (v + 1.f) * (H * 0.5f) - 0.5f;
        float x0f = floorf(gx), y0f = floorf(gy);
        float wx1 = gx - x0f, wy1 = gy - y0f;
        bool vx0 = (x0f >= 0.f)       && (x0f <= (float)(W - 1));
        bool vx1 = (x0f + 1.f >= 0.f) && (x0f + 1.f <= (float)(W - 1));
        bool vy0 = (y0f >= 0.f)       && (y0f <= (float)(H - 1));
        bool vy1 = (y0f + 1.f >= 0.f) && (y0f + 1.f <= (float)(H - 1));
        flag = ((vx0 || vx1) && (vy0 || vy1)) ? 1 : 0;
        int x0 = (int)fminf(fmaxf(x0f, 0.f),       (float)(W - 1));
        int x1 = (int)fminf(fmaxf(x0f + 1.f, 0.f), (float)(W - 1));
        int y0 = (int)fminf(fmaxf(y0f, 0.f),       (float)(H - 1));
        int y1 = (int)fminf(fmaxf(y0f + 1.f, 0.f), (float)(H - 1));
        dA.x = PBl[lvl] + (b * NCAM + cam) * HWl[lvl] + y0 * W + x0;  // pixel index
        dA.y = (x1 - x0) * 256;                                       // float offset
        dA.z = (y1 - y0) * W * 256;
        dA.w = ((cam * NLVL + lvl) * NPT + p) * NGRP;
        dW.x = (vx0 && vy0) ? (1.f - wx1) * (1.f - wy1) : 0.f;
        dW.y = (vx1 && vy0) ? wx1 * (1.f - wy1)         : 0.f;
        dW.z = (vx0 && vy1) ? (1.f - wx1) * wy1         : 0.f;
        dW.w = (vx1 && vy1) ? wx1 * wy1                 : 0.f;
    }

    // deterministic compaction directly into descriptor arrays
    unsigned bal = 0;
    if (wrp < 6) {
        bal = __ballot_sync(0xffffffffu, flag);
        if (lane == 0) s_wcnt[wrp] = __popc(bal);
    } else {
        if (lane == 0) s_wcnt[wrp] = 0;
    }
    __syncthreads();
    if (wrp < 6 && flag) {
        int base = 0;
        for (int w2 = 0; w2 < wrp; w2++) base += s_wcnt[w2];
        int pos = base + __popc(bal & ((1u << lane) - 1u));
        s_dA[pos] = dA;
        s_dW[pos] = dW;
    }
    __syncthreads();
    int cnt = s_wcnt[0] + s_wcnt[1] + s_wcnt[2] + s_wcnt[3] + s_wcnt[4] + s_wcnt[5];

    // coalesced gather + fuse
    const int g = wrp;
    float acc = 0.f;
#pragma unroll 2
    for (int i = 0; i < cnt; i++) {
        int4 D = s_dA[i];
        float4 wt = s_dW[i];
        const float* basep = g_nhwc + (((size_t)D.x) << 8) + c;
        float v00 = basep[0];
        float v01 = basep[D.y];
        float v10 = basep[D.z];
        float v11 = basep[D.z + D.y];
        float s = fmaf(wt.x, v00, fmaf(wt.y, v01, fmaf(wt.z, v10, wt.w * v11)));
        acc = fmaf(s, s_w[D.w + g], acc);
    }
    g_fusedT[(size_t)c * NBA + ba] = acc;
}

// =====================================================================
// Out-projection SGEMM-TN, 64x64 tile (better wave fill for N=256).
// =====================================================================
__global__ void __launch_bounds__(128) sgemm_tn64(
    const float* __restrict__ AT, const float* __restrict__ BT,
    const float* __restrict__ bias, float* __restrict__ C,
    int M, int N)
{
    __shared__ float As[32][64];
    __shared__ float Bs[32][64];
    const int bm0 = blockIdx.y * 64;
    const int bn0 = blockIdx.x * 64;
    const int tid  = threadIdx.x;
    const int w    = tid >> 5;
    const int lane = tid & 31;
    const int ry   = lane >> 3;
    const int rx   = lane & 7;
    const int m0   = w * 16 + ry * 4;
    const int n0   = rx * 8;

    float acc[4][8];
#pragma unroll
    for (int i = 0; i < 4; i++)
#pragma unroll
        for (int j = 0; j < 8; j++) acc[i][j] = 0.f;

    for (int kt = 0; kt < 256; kt += 32) {
#pragma unroll
        for (int s = 0; s < 4; s++) {
            int id = tid + s * 128;
            int k = id >> 4, mq = id & 15;
            int m = bm0 + mq * 4;
            float4 v = make_float4(0.f, 0.f, 0.f, 0.f);
            if (m < M) v = *(const float4*)(AT + (size_t)(kt + k) * M + m);
            *(float4*)&As[k][mq * 4] = v;
        }
#pragma unroll
        for (int s = 0; s < 4; s++) {
            int id = tid + s * 128;
            int k = id >> 4, nq = id & 15;
            *(float4*)&Bs[k][nq * 4] =
                *(const float4*)(BT + (size_t)(kt + k) * N + bn0 + nq * 4);
        }
        __syncthreads();

#pragma unroll
        for (int k = 0; k < 32; k++) {
            float4 a0 = *(const float4*)&As[k][m0];
            float4 b0 = *(const float4*)&Bs[k][n0];
            float4 b1 = *(const float4*)&Bs[k][n0 + 4];
            float am[4] = {a0.x, a0.y, a0.z, a0.w};
            float bv[8] = {b0.x, b0.y, b0.z, b0.w, b1.x, b1.y, b1.z, b1.w};
#pragma unroll
            for (int i = 0; i < 4; i++)
#pragma unroll
                for (int j = 0; j < 8; j++)
                    acc[i][j] = fmaf(am[i], bv[j], acc[i][j]);
        }
        __syncthreads();
    }

    float4 bb0 = *(const float4*)(bias + bn0 + n0);
    float4 bb1 = *(const float4*)(bias + bn0 + n0 + 4);
    float bv[8] = {bb0.x, bb0.y, bb0.z, bb0.w, bb1.x, bb1.y, bb1.z, bb1.w};
#pragma unroll
    for (int i = 0; i < 4; i++) {
        int m = bm0 + m0 + i;
        if (m >= M) continue;
        float4 o0, o1;
        o0.x = acc[i][0] + bv[0]; o0.y = acc[i][1] + bv[1];
        o0.z = acc[i][2] + bv[2]; o0.w = acc[i][3] + bv[3];
        o1.x = acc[i][4] + bv[4]; o1.y = acc[i][5] + bv[5];
        o1.z = acc[i][6] + bv[6]; o1.w = acc[i][7] + bv[7];
        *(float4*)(C + (size_t)m * N + bn0 + n0)     = o0;
        *(float4*)(C + (size_t)m * N + bn0 + n0 + 4) = o1;
    }
}

// =====================================================================
// launch
// =====================================================================
extern "C" void kernel_launch(void* const* d_in, const int* in_sizes, int n_in,
                              void* d_out, int out_size)
{
    const float* inst   = (const float*)d_in[0];
    const float* anchor = (const float*)d_in[1];
    const float* emb    = (const float*)d_in[2];
    const float* f0     = (const float*)d_in[3];
    const float* f1     = (const float*)d_in[4];
    const float* f2     = (const float*)d_in[5];
    const float* f3     = (const float*)d_in[6];
    const float* proj   = (const float*)d_in[7];
    const float* wh     = (const float*)d_in[8];
    const float* w_fc   = (const float*)d_in[9];
    const float* b_fc   = (const float*)d_in[10];
    const float* w_out  = (const float*)d_in[11];
    const float* b_out  = (const float*)d_in[12];
    float* out = (float*)d_out;

    float *featT, *wfcT, *woutT, *gw, *fusedT;
    cudaGetSymbolAddress((void**)&featT,  g_featT);
    cudaGetSymbolAddress((void**)&wfcT,   g_wfcT);
    cudaGetSymbolAddress((void**)&woutT,  g_woutT);
    cudaGetSymbolAddress((void**)&gw,     g_w);
    cudaGetSymbolAddress((void**)&fusedT, g_fusedT);

    // 1) merged transposes
    prep_kernel<<<456 + 336 + 64, dim3(32, 8)>>>(inst, emb, w_fc, w_out,
                                                 featT, wfcT, woutT);
    // 2) FC GEMM + NHWC conversion in one launch (overlapping pipes)
    mega_kernel<<<GEMM_BLKS + CVTOT, 128>>>(featT, wfcT, b_fc, gw, f0, f1, f2, f3);
    // 3) fused softmax + projection + coalesced sampling + fusion
    agg_kernel<<<NBA, 256>>>(anchor, proj, wh);
    // 4) out-projection
    sgemm_tn64<<<dim3(EDD / 64, (NBA + 63) / 64), 128>>>(fusedT, woutT, b_out, out, NBA, EDD);
}

// round 5
// speedup vs baseline: 1.4817x; 1.4817x over previous
#include <cuda_runtime.h>
#include <math.h>

// ----- problem constants -----
#define BB    2
#define AA    900
#define EDD   256
#define NGRP  8
#define NCAM  6
#define NLVL  4
#define NPT   7
#define NW    1344            // NGRP*NCAM*NLVL*NPT
#define NBA   (BB*AA)         // 1800
#define NDESC (NCAM*NPT*NLVL) // 168
#define NBC   (BB*NCAM)       // 12

// level geometry
#define HW0 11264
#define HW1 2816
#define HW2 704
#define HW3 176
// pixel bases in unified NHWC buffer
#define PB0 0
#define PB1 (NBC*HW0)
#define PB2 (PB1 + NBC*HW1)
#define PB3 (PB2 + NBC*HW2)
#define NPIX (PB3 + NBC*HW3)           // 179520

// conversion blocks: per level NBC * pixTiles(64) * chTiles(4)
#define CT0 176
#define CT1 44
#define CT2 11
#define CT3 3
#define CV0 (NBC*CT0*4)   // 8448
#define CV1 (NBC*CT1*4)   // 2112
#define CV2 (NBC*CT2*4)   // 528
#define CV3 (NBC*CT3*4)   // 144
#define CVTOT (CV0+CV1+CV2+CV3)        // 11232

#define GEMM_BLKS ((NW/64) * ((NBA+127)/128))   // 21*15 = 315
#define SPLITK 4

// ----- scratch (allocation-free: device globals) -----
__device__ float g_featT[EDD * NBA];
__device__ float g_wfcT[EDD * NW];
__device__ float g_woutT[EDD * EDD];
__device__ float g_w[NBA * NW];
__device__ float g_fusedT[EDD * NBA];
__device__ float g_part[SPLITK * NBA * EDD];
__device__ float g_nhwc[(size_t)NPIX * EDD];   // ~184MB

// =====================================================================
// Prep: three transposes merged.  block (32,8).
// =====================================================================
__device__ __forceinline__ void do_transpose(
    const float* in, const float* in2, float* out, int M,
    int bx, int by, bool add2)
{
    __shared__ float t[32][33];
    const int k0 = bx * 32;
    const int m0 = by * 32;
    const int tx = threadIdx.x, ty = threadIdx.y;
#pragma unroll
    for (int j = ty; j < 32; j += 8) {
        int m = m0 + j;
        float v = 0.f;
        if (m < M) {
            v = in[(size_t)m * 256 + k0 + tx];
            if (add2) v += in2[(size_t)m * 256 + k0 + tx];
        }
        t[j][tx] = v;
    }
    __syncthreads();
#pragma unroll
    for (int j = ty; j < 32; j += 8) {
        int m = m0 + tx;
        if (m < M) out[(size_t)(k0 + j) * M + m] = t[tx][j];
    }
}

__global__ void __launch_bounds__(256) prep_kernel(
    const float* __restrict__ inst, const float* __restrict__ emb,
    const float* __restrict__ w_fc, const float* __restrict__ w_out,
    float* __restrict__ featT, float* __restrict__ wfcT, float* __restrict__ woutT)
{
    int bid = blockIdx.x;
    if (bid < 456) {
        do_transpose(inst, emb, featT, NBA, bid % 8, bid / 8, true);
    } else if (bid < 456 + 336) {
        bid -= 456;
        do_transpose(w_fc, 0, wfcT, NW, bid % 8, bid / 8, false);
    } else {
        bid -= 456 + 336;
        do_transpose(w_out, 0, woutT, EDD, bid % 8, bid / 8, false);
    }
}

// =====================================================================
// Mega kernel (256 threads/block):
//   blocks [0, GEMM_BLKS): FC GEMM  C[1800][1344] = AT^T @ BT + bias
//   blocks [GEMM_BLKS, +CVTOT): NCHW->NHWC conversion, float4 both sides
// =====================================================================
__global__ void __launch_bounds__(256) mega_kernel(
    const float* __restrict__ AT, const float* __restrict__ BT,
    const float* __restrict__ bias, float* __restrict__ C,
    const float* __restrict__ f0, const float* __restrict__ f1,
    const float* __restrict__ f2, const float* __restrict__ f3)
{
    __shared__ float sm[6144];   // GEMM: 4096 + 2048; conv: 64x65 = 4160
    const int tid = threadIdx.x;

    if (blockIdx.x < GEMM_BLKS) {
        const int gx = blockIdx.x % (NW / 64);
        const int gy = blockIdx.x / (NW / 64);
        const int bm0 = gy * 128;
        const int bn0 = gx * 64;
        const int wid   = tid >> 5;
        const int lane  = tid & 31;
        const int warpM = wid & 3;          // 0..3 (32 rows each)
        const int warpN = wid >> 2;         // 0..1 (32 cols each)
        const int m0 = warpM * 32 + (lane >> 2) * 4;   // 4 rows
        const int n0 = warpN * 32 + (lane & 3) * 8;    // 8 cols
        const int M = NBA, N = NW;

        float acc[4][8];
#pragma unroll
        for (int i = 0; i < 4; i++)
#pragma unroll
            for (int j = 0; j < 8; j++) acc[i][j] = 0.f;

        for (int kt = 0; kt < 256; kt += 32) {
#pragma unroll
            for (int s = 0; s < 4; s++) {
                int id = tid + s * 256;
                int k = id >> 5, mq = id & 31;
                int m = bm0 + mq * 4;
                float4 v = make_float4(0.f, 0.f, 0.f, 0.f);
                if (m < M) v = *(const float4*)(AT + (size_t)(kt + k) * M + m);
                *(float4*)&sm[k * 128 + mq * 4] = v;
            }
#pragma unroll
            for (int s = 0; s < 2; s++) {
                int id = tid + s * 256;
                int k = id >> 4, nq = id & 15;
                *(float4*)&sm[4096 + k * 64 + nq * 4] =
                    *(const float4*)(BT + (size_t)(kt + k) * N + bn0 + nq * 4);
            }
            __syncthreads();

#pragma unroll
            for (int k = 0; k < 32; k++) {
                float4 a  = *(const float4*)&sm[k * 128 + m0];
                float4 b0 = *(const float4*)&sm[4096 + k * 64 + n0];
                float4 b1 = *(const float4*)&sm[4096 + k * 64 + n0 + 4];
                float am[4] = {a.x, a.y, a.z, a.w};
                float bv[8] = {b0.x, b0.y, b0.z, b0.w, b1.x, b1.y, b1.z, b1.w};
#pragma unroll
                for (int i = 0; i < 4; i++)
#pragma unroll
                    for (int j = 0; j < 8; j++)
                        acc[i][j] = fmaf(am[i], bv[j], acc[i][j]);
            }
            __syncthreads();
        }

        float4 bb0 = *(const float4*)(bias + bn0 + n0);
        float4 bb1 = *(const float4*)(bias + bn0 + n0 + 4);
        float bv[8] = {bb0.x, bb0.y, bb0.z, bb0.w, bb1.x, bb1.y, bb1.z, bb1.w};
#pragma unroll
        for (int i = 0; i < 4; i++) {
            int m = bm0 + m0 + i;
            if (m >= M) continue;
            float4 o0, o1;
            o0.x = acc[i][0] + bv[0]; o0.y = acc[i][1] + bv[1];
            o0.z = acc[i][2] + bv[2]; o0.w = acc[i][3] + bv[3];
            o1.x = acc[i][4] + bv[4]; o1.y = acc[i][5] + bv[5];
            o1.z = acc[i][6] + bv[6]; o1.w = acc[i][7] + bv[7];
            *(float4*)(C + (size_t)m * N + bn0 + n0)     = o0;
            *(float4*)(C + (size_t)m * N + bn0 + n0 + 4) = o1;
        }
    } else {
        // ---------------- NCHW -> NHWC, 64ch x 64px tile ----------------
        int cb = blockIdx.x - GEMM_BLKS;
        const float* fin; int HWl, tilesHW, pbase;
        if (cb < CV0)               { fin = f0; HWl = HW0; tilesHW = CT0; pbase = PB0; }
        else if ((cb -= CV0) < CV1) { fin = f1; HWl = HW1; tilesHW = CT1; pbase = PB1; }
        else if ((cb -= CV1) < CV2) { fin = f2; HWl = HW2; tilesHW = CT2; pbase = PB2; }
        else       { cb -= CV2;       fin = f3; HWl = HW3; tilesHW = CT3; pbase = PB3; }
        const int nt  = tilesHW * 4;
        const int bc  = cb / nt;
        const int r   = cb % nt;
        const int hw0 = (r >> 2) * 64;
        const int c0  = (r & 3) * 64;
        float (*t)[65] = (float(*)[65])sm;

        const float* ip = fin + (size_t)bc * 256 * HWl;
#pragma unroll
        for (int s = 0; s < 4; s++) {
            int id = tid + s * 256;
            int row = id >> 4, q = id & 15;
            int hw = hw0 + q * 4;
            if (hw < HWl) {
                float4 v = *(const float4*)(ip + (size_t)(c0 + row) * HWl + hw);
                t[row][q * 4 + 0] = v.x;
                t[row][q * 4 + 1] = v.y;
                t[row][q * 4 + 2] = v.z;
                t[row][q * 4 + 3] = v.w;
            }
        }
        __syncthreads();
        float* op = g_nhwc + ((size_t)(pbase + bc * HWl)) * 256;
#pragma unroll
        for (int s = 0; s < 4; s++) {
            int id = tid + s * 256;
            int px = id >> 4, qc = id & 15;
            int hw = hw0 + px;
            if (hw < HWl) {
                float4 o;
                o.x = t[qc * 4 + 0][px];
                o.y = t[qc * 4 + 1][px];
                o.z = t[qc * 4 + 2][px];
                o.w = t[qc * 4 + 3][px];
                *(float4*)(op + (size_t)hw * 256 + c0 + qc * 4) = o;
            }
        }
    }
}

// =====================================================================
// Fused aggregation (NHWC gathers)
// =====================================================================
__global__ void __launch_bounds__(256) agg_kernel(
    const float* __restrict__ anchor, const float* __restrict__ proj,
    const float* __restrict__ wh)
{
    __shared__ float  s_w[NW];
    __shared__ float  s_uv[NCAM * NPT][2];
    __shared__ int4   s_dA[NDESC];
    __shared__ float4 s_dW[NDESC];
    __shared__ int    s_wcnt[8];

    const int ba   = blockIdx.x;
    const int b    = ba / AA;
    const int tid  = threadIdx.x;
    const int c    = tid;
    const int wrp  = tid >> 5;
    const int lane = tid & 31;

    for (int i = tid; i < NW; i += 256) s_w[i] = g_w[(size_t)ba * NW + i];

    if (tid < NCAM * NPT) {
        const float fsx[7] = {0.f, 0.45f, -0.45f, 0.f, 0.f, 0.f, 0.f};
        const float fsy[7] = {0.f, 0.f, 0.f, 0.45f, -0.45f, 0.f, 0.f};
        const float fsz[7] = {0.f, 0.f, 0.f, 0.f, 0.f, 0.45f, -0.45f};
        int cam = tid / NPT, p = tid % NPT;
        const float* an = anchor + (size_t)ba * 8;
        float e0 = expf(an[3]), e1 = expf(an[4]), e2 = expf(an[5]);
        float k0 = fsx[p] * e0, k1 = fsy[p] * e1, k2 = fsz[p] * e2;
        float sn = an[6], cs = an[7];
        float X = cs * k0 - sn * k1 + an[0];
        float Y = sn * k0 + cs * k1 + an[1];
        float Z = k2 + an[2];
        const float* M = proj + (size_t)(b * NCAM + cam) * 16;
        float d0 = M[0] * X + M[1] * Y + M[2]  * Z + M[3];
        float d1 = M[4] * X + M[5] * Y + M[6]  * Z + M[7];
        float d2 = M[8] * X + M[9] * Y + M[10] * Z + M[11];
        float iz = 1.f / fmaxf(d2, 1e-5f);
        float x = d0 * iz / fmaxf(wh[(size_t)(b * NCAM + cam) * 2 + 0], 1e-5f);
        float y = d1 * iz / fmaxf(wh[(size_t)(b * NCAM + cam) * 2 + 1], 1e-5f);
        s_uv[tid][0] = x * 2.f - 1.f;
        s_uv[tid][1] = y * 2.f - 1.f;
    }
    __syncthreads();

    {
        float mx = -INFINITY;
        for (int cc = lane; cc < 168; cc += 32) mx = fmaxf(mx, s_w[cc * 8 + wrp]);
#pragma unroll
        for (int o = 16; o; o >>= 1) mx = fmaxf(mx, __shfl_xor_sync(0xffffffffu, mx, o));
        float sum = 0.f;
        for (int cc = lane; cc < 168; cc += 32) {
            float e = expf(s_w[cc * 8 + wrp] - mx);
            s_w[cc * 8 + wrp] = e;
            sum += e;
        }
#pragma unroll
        for (int o = 16; o; o >>= 1) sum += __shfl_xor_sync(0xffffffffu, sum, o);
        float inv = 1.f / sum;
        for (int cc = lane; cc < 168; cc += 32) s_w[cc * 8 + wrp] *= inv;
    }

    const int Hl[4]  = {64, 32, 16, 8};
    const int Wl[4]  = {176, 88, 44, 22};
    const int HWl[4] = {HW0, HW1, HW2, HW3};
    const int PBl[4] = {PB0, PB1, PB2, PB3};
    int flag = 0;
    int4 dA; float4 dW;
    if (tid < NDESC) {
        int d = tid;
        int cam = d / (NPT * NLVL);
        int r   = d - cam * (NPT * NLVL);
        int p   = r >> 2;
        int lvl = r & 3;
        float u = s_uv[cam * NPT + p][0];
        float v = s_uv[cam * NPT + p][1];
        const int H = Hl[lvl], W = Wl[lvl];
        float gx = (u + 1.f) * (W * 0.5f) - 0.5f;
        float gy = (v + 1.f) * (H * 0.5f) - 0.5f;
        float x0f = floorf(gx), y0f = floorf(gy);
        float wx1 = gx - x0f, wy1 = gy - y0f;
        bool vx0 = (x0f >= 0.f)       && (x0f <= (float)(W - 1));
        bool vx1 = (x0f + 1.f >= 0.f) && (x0f + 1.f <= (float)(W - 1));
        bool vy0 = (y0f >= 0.f)       && (y0f <= (float)(H - 1));
        bool vy1 = (y0f + 1.f >= 0.f) && (y0f + 1.f <= (float)(H - 1));
        flag = ((vx0 || vx1) && (vy0 || vy1)) ? 1 : 0;
        int x0 = (int)fminf(fmaxf(x0f, 0.f),       (float)(W - 1));
        int x1 = (int)fminf(fmaxf(x0f + 1.f, 0.f), (float)(W - 1));
        int y0 = (int)fminf(fmaxf(y0f, 0.f),       (float)(H - 1));
        int y1 = (int)fminf(fmaxf(y0f + 1.f, 0.f), (float)(H - 1));
        dA.x = PBl[lvl] + (b * NCAM + cam) * HWl[lvl] + y0 * W + x0;
        dA.y = (x1 - x0) * 256;
        dA.z = (y1 - y0) * W * 256;
        dA.w = ((cam * NLVL + lvl) * NPT + p) * NGRP;
        dW.x = (vx0 && vy0) ? (1.f - wx1) * (1.f - wy1) : 0.f;
        dW.y = (vx1 && vy0) ? wx1 * (1.f - wy1)         : 0.f;
        dW.z = (vx0 && vy1) ? (1.f - wx1) * wy1         : 0.f;
        dW.w = (vx1 && vy1) ? wx1 * wy1                 : 0.f;
    }

    unsigned bal = 0;
    if (wrp < 6) {
        bal = __ballot_sync(0xffffffffu, flag);
        if (lane == 0) s_wcnt[wrp] = __popc(bal);
    } else {
        if (lane == 0) s_wcnt[wrp] = 0;
    }
    __syncthreads();
    if (wrp < 6 && flag) {
        int base = 0;
        for (int w2 = 0; w2 < wrp; w2++) base += s_wcnt[w2];
        int pos = base + __popc(bal & ((1u << lane) - 1u));
        s_dA[pos] = dA;
        s_dW[pos] = dW;
    }
    __syncthreads();
    int cnt = s_wcnt[0] + s_wcnt[1] + s_wcnt[2] + s_wcnt[3] + s_wcnt[4] + s_wcnt[5];

    const int g = wrp;
    float acc = 0.f;
#pragma unroll 2
    for (int i = 0; i < cnt; i++) {
        int4 D = s_dA[i];
        float4 wt = s_dW[i];
        const float* basep = g_nhwc + (((size_t)D.x) << 8) + c;
        float v00 = basep[0];
        float v01 = basep[D.y];
        float v10 = basep[D.z];
        float v11 = basep[D.z + D.y];
        float s = fmaf(wt.x, v00, fmaf(wt.y, v01, fmaf(wt.z, v10, wt.w * v11)));
        acc = fmaf(s, s_w[D.w + g], acc);
    }
    g_fusedT[(size_t)c * NBA + ba] = acc;
}

// =====================================================================
// Out-projection, split-K=4: partial[z] = AT[zK..]^T @ BT[zK..]
// tile 64x64, 256 threads, micro 4x4.
// =====================================================================
__global__ void __launch_bounds__(256) outproj_splitk(
    const float* __restrict__ AT, const float* __restrict__ BT,
    float* __restrict__ P)
{
    __shared__ float As[32][64];
    __shared__ float Bs[32][64];
    const int bn0 = blockIdx.x * 64;
    const int bm0 = blockIdx.y * 64;
    const int kz  = blockIdx.z;
    const int tid  = threadIdx.x;
    const int wid  = tid >> 5;
    const int lane = tid & 31;
    const int warpM = wid & 3;          // 0..3 (16 rows)
    const int warpN = wid >> 2;         // 0..1 (32 cols)
    const int m0 = warpM * 16 + (lane >> 3) * 4;
    const int n0 = warpN * 32 + (lane & 7) * 4;
    const int M = NBA, N = EDD;

    float acc[4][4];
#pragma unroll
    for (int i = 0; i < 4; i++)
#pragma unroll
        for (int j = 0; j < 4; j++) acc[i][j] = 0.f;

    for (int kt = kz * 64; kt < kz * 64 + 64; kt += 32) {
#pragma unroll
        for (int s = 0; s < 2; s++) {
            int id = tid + s * 256;
            int k = id >> 4, mq = id & 15;
            int m = bm0 + mq * 4;
            float4 v = make_float4(0.f, 0.f, 0.f, 0.f);
            if (m < M) v = *(const float4*)(AT + (size_t)(kt + k) * M + m);
            *(float4*)&As[k][mq * 4] = v;
        }
#pragma unroll
        for (int s = 0; s < 2; s++) {
            int id = tid + s * 256;
            int k = id >> 4, nq = id & 15;
            *(float4*)&Bs[k][nq * 4] =
                *(const float4*)(BT + (size_t)(kt + k) * N + bn0 + nq * 4);
        }
        __syncthreads();

#pragma unroll
        for (int k = 0; k < 32; k++) {
            float4 a = *(const float4*)&As[k][m0];
            float4 bq = *(const float4*)&Bs[k][n0];
            float am[4] = {a.x, a.y, a.z, a.w};
            float bv[4] = {bq.x, bq.y, bq.z, bq.w};
#pragma unroll
            for (int i = 0; i < 4; i++)
#pragma unroll
                for (int j = 0; j < 4; j++)
                    acc[i][j] = fmaf(am[i], bv[j], acc[i][j]);
        }
        __syncthreads();
    }

#pragma unroll
    for (int i = 0; i < 4; i++) {
        int m = bm0 + m0 + i;
        if (m >= M) continue;
        float4 o = make_float4(acc[i][0], acc[i][1], acc[i][2], acc[i][3]);
        *(float4*)(P + ((size_t)kz * M + m) * N + bn0 + n0) = o;
    }
}

__global__ void __launch_bounds__(256) reduce_out(
    const float* __restrict__ bias, float* __restrict__ out)
{
    int idx = blockIdx.x * 256 + threadIdx.x;     // float4 index
    if (idx >= NBA * EDD / 4) return;
    int e = idx * 4;
    int col = e & 255;
    const float* P = g_part;
    float4 r0 = *(const float4*)(P + e);
    float4 r1 = *(const float4*)(P + (size_t)NBA * EDD + e);
    float4 r2 = *(const float4*)(P + (size_t)2 * NBA * EDD + e);
    float4 r3 = *(const float4*)(P + (size_t)3 * NBA * EDD + e);
    float4 bb = *(const float4*)(bias + col);
    float4 o;
    o.x = r0.x + r1.x + r2.x + r3.x + bb.x;
    o.y = r0.y + r1.y + r2.y + r3.y + bb.y;
    o.z = r0.z + r1.z + r2.z + r3.z + bb.z;
    o.w = r0.w + r1.w + r2.w + r3.w + bb.w;
    *(float4*)(out + e) = o;
}

// =====================================================================
// launch
// =====================================================================
extern "C" void kernel_launch(void* const* d_in, const int* in_sizes, int n_in,
                              void* d_out, int out_size)
{
    const float* inst   = (const float*)d_in[0];
    const float* anchor = (const float*)d_in[1];
    const float* emb    = (const float*)d_in[2];
    const float* f0     = (const float*)d_in[3];
    const float* f1     = (const float*)d_in[4];
    const float* f2     = (const float*)d_in[5];
    const float* f3     = (const float*)d_in[6];
    const float* proj   = (const float*)d_in[7];
    const float* wh     = (const float*)d_in[8];
    const float* w_fc   = (const float*)d_in[9];
    const float* b_fc   = (const float*)d_in[10];
    const float* w_out  = (const float*)d_in[11];
    const float* b_out  = (const float*)d_in[12];
    float* out = (float*)d_out;

    float *featT, *wfcT, *woutT, *gw, *fusedT, *part;
    cudaGetSymbolAddress((void**)&featT,  g_featT);
    cudaGetSymbolAddress((void**)&wfcT,   g_wfcT);
    cudaGetSymbolAddress((void**)&woutT,  g_woutT);
    cudaGetSymbolAddress((void**)&gw,     g_w);
    cudaGetSymbolAddress((void**)&fusedT, g_fusedT);
    cudaGetSymbolAddress((void**)&part,   g_part);

    prep_kernel<<<456 + 336 + 64, dim3(32, 8)>>>(inst, emb, w_fc, w_out,
                                                 featT, wfcT, woutT);
    mega_kernel<<<GEMM_BLKS + CVTOT, 256>>>(featT, wfcT, b_fc, gw, f0, f1, f2, f3);
    agg_kernel<<<NBA, 256>>>(anchor, proj, wh);
    outproj_splitk<<<dim3(EDD / 64, (NBA + 63) / 64, SPLITK), 256>>>(fusedT, woutT, part);
    reduce_out<<<(NBA * EDD / 4 + 255) / 256, 256>>>(b_out, out);
}

// round 6
// speedup vs baseline: 1.5464x; 1.0436x over previous
#include <cuda_runtime.h>
#include <cuda_fp16.h>
#include <math.h>

// ----- problem constants -----
#define BB    2
#define AA    900
#define EDD   256
#define NGRP  8
#define NCAM  6
#define NLVL  4
#define NPT   7
#define NW    1344            // NGRP*NCAM*NLVL*NPT
#define NBA   (BB*AA)         // 1800
#define NDESC (NCAM*NPT*NLVL) // 168
#define NBC   (BB*NCAM)       // 12

// level geometry
#define HW0 11264
#define HW1 2816
#define HW2 704
#define HW3 176
// pixel bases in unified NHWC buffer
#define PB0 0
#define PB1 (NBC*HW0)
#define PB2 (PB1 + NBC*HW1)
#define PB3 (PB2 + NBC*HW2)
#define NPIX (PB3 + NBC*HW3)           // 179520

// conversion blocks: per level NBC * pixTiles(64px) * chTiles(64ch)
#define CT0 176
#define CT1 44
#define CT2 11
#define CT3 3
#define CV0 (NBC*CT0*4)
#define CV1 (NBC*CT1*4)
#define CV2 (NBC*CT2*4)
#define CV3 (NBC*CT3*4)
#define CVTOT (CV0+CV1+CV2+CV3)        // 11232

#define GEMM_BLKS ((NW/64) * ((NBA+127)/128))   // 315
#define SPLITK 4

// ----- scratch (allocation-free: device globals) -----
__device__ __half g_featT[EDD * NBA];    // fp16 (inst+emb)^T
__device__ __half g_wfcT[EDD * NW];      // fp16 w_fc^T
__device__ float  g_woutT[EDD * EDD];    // fp32 w_out^T
__device__ float  g_w[NBA * NW];         // fp32 logits
__device__ float  g_fusedT[EDD * NBA];   // fp32 fused^T
__device__ float  g_part[SPLITK * NBA * EDD];
__device__ __half g_nhwc[(size_t)NPIX * EDD];  // fp16 NHWC features (~92MB)

// ----- helpers -----
__device__ __forceinline__ void stv(float* p, float v)  { *p = v; }
__device__ __forceinline__ void stv(__half* p, float v) { *p = __float2half_rn(v); }

__device__ __forceinline__ void h4tof(const __half* p, float* f) {
    __half2 h0 = *(const __half2*)(p);
    __half2 h1 = *(const __half2*)(p + 2);
    float2 x = __half22float2(h0), y = __half22float2(h1);
    f[0] = x.x; f[1] = x.y; f[2] = y.x; f[3] = y.y;
}

// =====================================================================
// Prep: three transposes merged.  block (32,8).
// =====================================================================
template<typename T>
__device__ __forceinline__ void do_transpose(
    const float* in, const float* in2, T* out, int M,
    int bx, int by, bool add2)
{
    __shared__ float t[32][33];
    const int k0 = bx * 32;
    const int m0 = by * 32;
    const int tx = threadIdx.x, ty = threadIdx.y;
#pragma unroll
    for (int j = ty; j < 32; j += 8) {
        int m = m0 + j;
        float v = 0.f;
        if (m < M) {
            v = in[(size_t)m * 256 + k0 + tx];
            if (add2) v += in2[(size_t)m * 256 + k0 + tx];
        }
        t[j][tx] = v;
    }
    __syncthreads();
#pragma unroll
    for (int j = ty; j < 32; j += 8) {
        int m = m0 + tx;
        if (m < M) stv(&out[(size_t)(k0 + j) * M + m], t[tx][j]);
    }
    __syncthreads();
}

__global__ void __launch_bounds__(256) prep_kernel(
    const float* __restrict__ inst, const float* __restrict__ emb,
    const float* __restrict__ w_fc, const float* __restrict__ w_out)
{
    int bid = blockIdx.x;
    if (bid < 456) {
        do_transpose<__half>(inst, emb, g_featT, NBA, bid % 8, bid / 8, true);
    } else if (bid < 456 + 336) {
        bid -= 456;
        do_transpose<__half>(w_fc, 0, g_wfcT, NW, bid % 8, bid / 8, false);
    } else {
        bid -= 456 + 336;
        do_transpose<float>(w_out, 0, g_woutT, EDD, bid % 8, bid / 8, false);
    }
}

// =====================================================================
// Mega kernel (256 threads/block):
//   blocks [0, GEMM_BLKS): fp16-operand FC GEMM (fp32 accum/out)
//   blocks [GEMM_BLKS, +CVTOT): NCHW fp32 -> NHWC fp16 conversion
// =====================================================================
__global__ void __launch_bounds__(256) mega_kernel(
    const float* __restrict__ bias, float* __restrict__ C,
    const float* __restrict__ f0, const float* __restrict__ f1,
    const float* __restrict__ f2, const float* __restrict__ f3)
{
    __shared__ __align__(16) unsigned char smraw[16896];
    const int tid = threadIdx.x;

    if (blockIdx.x < GEMM_BLKS) {
        __half* As = (__half*)smraw;            // [32][128] = 8KB
        __half* Bs = (__half*)(smraw + 8192);   // [32][64]  = 4KB
        const __half* AT = g_featT;
        const __half* BT = g_wfcT;
        const int gx = blockIdx.x % (NW / 64);
        const int gy = blockIdx.x / (NW / 64);
        const int bm0 = gy * 128;
        const int bn0 = gx * 64;
        const int wid   = tid >> 5;
        const int lane  = tid & 31;
        const int warpM = wid & 3;
        const int warpN = wid >> 2;
        const int m0 = warpM * 32 + (lane >> 2) * 4;
        const int n0 = warpN * 32 + (lane & 3) * 8;
        const int M = NBA, N = NW;

        float acc[4][8];
#pragma unroll
        for (int i = 0; i < 4; i++)
#pragma unroll
            for (int j = 0; j < 8; j++) acc[i][j] = 0.f;

        for (int kt = 0; kt < 256; kt += 32) {
            // stage A: 32k x 128m halves (raw copy)
#pragma unroll
            for (int s = 0; s < 4; s++) {
                int id = tid + s * 256;
                int k = id >> 5, mq = id & 31;
                int m = bm0 + mq * 4;
                uint2 v = make_uint2(0u, 0u);
                if (m < M) v = *(const uint2*)(AT + (size_t)(kt + k) * M + m);
                *(uint2*)&As[k * 128 + mq * 4] = v;
            }
            // stage B: 32k x 64n halves
#pragma unroll
            for (int s = 0; s < 2; s++) {
                int id = tid + s * 256;
                int k = id >> 4, nq = id & 15;
                *(uint2*)&Bs[k * 64 + nq * 4] =
                    *(const uint2*)(BT + (size_t)(kt + k) * N + bn0 + nq * 4);
            }
            __syncthreads();

#pragma unroll
            for (int k = 0; k < 32; k++) {
                float am[4], bv[8];
                h4tof(&As[k * 128 + m0], am);
                h4tof(&Bs[k * 64 + n0], bv);
                h4tof(&Bs[k * 64 + n0 + 4], bv + 4);
#pragma unroll
                for (int i = 0; i < 4; i++)
#pragma unroll
                    for (int j = 0; j < 8; j++)
                        acc[i][j] = fmaf(am[i], bv[j], acc[i][j]);
            }
            __syncthreads();
        }

        float4 bb0 = *(const float4*)(bias + bn0 + n0);
        float4 bb1 = *(const float4*)(bias + bn0 + n0 + 4);
        float bv[8] = {bb0.x, bb0.y, bb0.z, bb0.w, bb1.x, bb1.y, bb1.z, bb1.w};
#pragma unroll
        for (int i = 0; i < 4; i++) {
            int m = bm0 + m0 + i;
            if (m >= M) continue;
            float4 o0, o1;
            o0.x = acc[i][0] + bv[0]; o0.y = acc[i][1] + bv[1];
            o0.z = acc[i][2] + bv[2]; o0.w = acc[i][3] + bv[3];
            o1.x = acc[i][4] + bv[4]; o1.y = acc[i][5] + bv[5];
            o1.z = acc[i][6] + bv[6]; o1.w = acc[i][7] + bv[7];
            *(float4*)(C + (size_t)m * N + bn0 + n0)     = o0;
            *(float4*)(C + (size_t)m * N + bn0 + n0 + 4) = o1;
        }
    } else {
        // ------- NCHW fp32 -> NHWC fp16, 64ch x 64px tile ---------------
        int cb = blockIdx.x - GEMM_BLKS;
        const float* fin; int HWl, tilesHW, pbase;
        if (cb < CV0)               { fin = f0; HWl = HW0; tilesHW = CT0; pbase = PB0; }
        else if ((cb -= CV0) < CV1) { fin = f1; HWl = HW1; tilesHW = CT1; pbase = PB1; }
        else if ((cb -= CV1) < CV2) { fin = f2; HWl = HW2; tilesHW = CT2; pbase = PB2; }
        else       { cb -= CV2;       fin = f3; HWl = HW3; tilesHW = CT3; pbase = PB3; }
        const int nt  = tilesHW * 4;
        const int bc  = cb / nt;
        const int r   = cb % nt;
        const int hw0 = (r >> 2) * 64;
        const int c0  = (r & 3) * 64;
        float (*t)[65] = (float(*)[65])smraw;   // 64*65*4 = 16640B

        const float* ip = fin + (size_t)bc * 256 * HWl;
#pragma unroll
        for (int s = 0; s < 4; s++) {
            int id = tid + s * 256;
            int row = id >> 4, q = id & 15;
            int hw = hw0 + q * 4;
            if (hw < HWl) {
                float4 v = *(const float4*)(ip + (size_t)(c0 + row) * HWl + hw);
                t[row][q * 4 + 0] = v.x;
                t[row][q * 4 + 1] = v.y;
                t[row][q * 4 + 2] = v.z;
                t[row][q * 4 + 3] = v.w;
            }
        }
        __syncthreads();
        __half* op = g_nhwc + ((size_t)(pbase + bc * HWl)) * 256;
#pragma unroll
        for (int s = 0; s < 4; s++) {
            int id = tid + s * 256;
            int px = id >> 4, qc = id & 15;
            int hw = hw0 + px;
            if (hw < HWl) {
                __half2 h0 = __floats2half2_rn(t[qc * 4 + 0][px], t[qc * 4 + 1][px]);
                __half2 h1 = __floats2half2_rn(t[qc * 4 + 2][px], t[qc * 4 + 3][px]);
                __half2* dst = (__half2*)(op + (size_t)hw * 256 + c0 + qc * 4);
                dst[0] = h0;
                dst[1] = h1;
            }
        }
    }
}

// =====================================================================
// Fused aggregation (fp16 NHWC gathers, fp32 math)
// =====================================================================
__global__ void __launch_bounds__(256) agg_kernel(
    const float* __restrict__ anchor, const float* __restrict__ proj,
    const float* __restrict__ wh)
{
    __shared__ float  s_w[NW];
    __shared__ float  s_uv[NCAM * NPT][2];
    __shared__ int4   s_dA[NDESC];
    __shared__ float4 s_dW[NDESC];
    __shared__ int    s_wcnt[8];

    const int ba   = blockIdx.x;
    const int b    = ba / AA;
    const int tid  = threadIdx.x;
    const int c    = tid;
    const int wrp  = tid >> 5;
    const int lane = tid & 31;

    for (int i = tid; i < NW; i += 256) s_w[i] = g_w[(size_t)ba * NW + i];

    if (tid < NCAM * NPT) {
        const float fsx[7] = {0.f, 0.45f, -0.45f, 0.f, 0.f, 0.f, 0.f};
        const float fsy[7] = {0.f, 0.f, 0.f, 0.45f, -0.45f, 0.f, 0.f};
        const float fsz[7] = {0.f, 0.f, 0.f, 0.f, 0.f, 0.45f, -0.45f};
        int cam = tid / NPT, p = tid % NPT;
        const float* an = anchor + (size_t)ba * 8;
        float e0 = expf(an[3]), e1 = expf(an[4]), e2 = expf(an[5]);
        float k0 = fsx[p] * e0, k1 = fsy[p] * e1, k2 = fsz[p] * e2;
        float sn = an[6], cs = an[7];
        float X = cs * k0 - sn * k1 + an[0];
        float Y = sn * k0 + cs * k1 + an[1];
        float Z = k2 + an[2];
        const float* M = proj + (size_t)(b * NCAM + cam) * 16;
        float d0 = M[0] * X + M[1] * Y + M[2]  * Z + M[3];
        float d1 = M[4] * X + M[5] * Y + M[6]  * Z + M[7];
        float d2 = M[8] * X + M[9] * Y + M[10] * Z + M[11];
        float iz = 1.f / fmaxf(d2, 1e-5f);
        float x = d0 * iz / fmaxf(wh[(size_t)(b * NCAM + cam) * 2 + 0], 1e-5f);
        float y = d1 * iz / fmaxf(wh[(size_t)(b * NCAM + cam) * 2 + 1], 1e-5f);
        s_uv[tid][0] = x * 2.f - 1.f;
        s_uv[tid][1] = y * 2.f - 1.f;
    }
    __syncthreads();

    {
        float mx = -INFINITY;
        for (int cc = lane; cc < 168; cc += 32) mx = fmaxf(mx, s_w[cc * 8 + wrp]);
#pragma unroll
        for (int o = 16; o; o >>= 1) mx = fmaxf(mx, __shfl_xor_sync(0xffffffffu, mx, o));
        float sum = 0.f;
        for (int cc = lane; cc < 168; cc += 32) {
            float e = expf(s_w[cc * 8 + wrp] - mx);
            s_w[cc * 8 + wrp] = e;
            sum += e;
        }
#pragma unroll
        for (int o = 16; o; o >>= 1) sum += __shfl_xor_sync(0xffffffffu, sum, o);
        float inv = 1.f / sum;
        for (int cc = lane; cc < 168; cc += 32) s_w[cc * 8 + wrp] *= inv;
    }

    const int Hl[4]  = {64, 32, 16, 8};
    const int Wl[4]  = {176, 88, 44, 22};
    const int HWl[4] = {HW0, HW1, HW2, HW3};
    const int PBl[4] = {PB0, PB1, PB2, PB3};
    int flag = 0;
    int4 dA; float4 dW;
    if (tid < NDESC) {
        int d = tid;
        int cam = d / (NPT * NLVL);
        int r   = d - cam * (NPT * NLVL);
        int p   = r >> 2;
        int lvl = r & 3;
        float u = s_uv[cam * NPT + p][0];
        float v = s_uv[cam * NPT + p][1];
        const int H = Hl[lvl], W = Wl[lvl];
        float gx = (u + 1.f) * (W * 0.5f) - 0.5f;
        float gy = (v + 1.f) * (H * 0.5f) - 0.5f;
        float x0f = floorf(gx), y0f = floorf(gy);
        float wx1 = gx - x0f, wy1 = gy - y0f;
        bool vx0 = (x0f >= 0.f)       && (x0f <= (float)(W - 1));
        bool vx1 = (x0f + 1.f >= 0.f) && (x0f + 1.f <= (float)(W - 1));
        bool vy0 = (y0f >= 0.f)       && (y0f <= (float)(H - 1));
        bool vy1 = (y0f + 1.f >= 0.f) && (y0f + 1.f <= (float)(H - 1));
        flag = ((vx0 || vx1) && (vy0 || vy1)) ? 1 : 0;
        int x0 = (int)fminf(fmaxf(x0f, 0.f),       (float)(W - 1));
        int x1 = (int)fminf(fmaxf(x0f + 1.f, 0.f), (float)(W - 1));
        int y0 = (int)fminf(fmaxf(y0f, 0.f),       (float)(H - 1));
        int y1 = (int)fminf(fmaxf(y0f + 1.f, 0.f), (float)(H - 1));
        dA.x = PBl[lvl] + (b * NCAM + cam) * HWl[lvl] + y0 * W + x0;
        dA.y = (x1 - x0) * 256;
        dA.z = (y1 - y0) * W * 256;
        dA.w = ((cam * NLVL + lvl) * NPT + p) * NGRP;
        dW.x = (vx0 && vy0) ? (1.f - wx1) * (1.f - wy1) : 0.f;
        dW.y = (vx1 && vy0) ? wx1 * (1.f - wy1)         : 0.f;
        dW.z = (vx0 && vy1) ? (1.f - wx1) * wy1         : 0.f;
        dW.w = (vx1 && vy1) ? wx1 * wy1                 : 0.f;
    }

    unsigned bal = 0;
    if (wrp < 6) {
        bal = __ballot_sync(0xffffffffu, flag);
        if (lane == 0) s_wcnt[wrp] = __popc(bal);
    } else {
        if (lane == 0) s_wcnt[wrp] = 0;
    }
    __syncthreads();
    if (wrp < 6 && flag) {
        int base = 0;
        for (int w2 = 0; w2 < wrp; w2++) base += s_wcnt[w2];
        int pos = base + __popc(bal & ((1u << lane) - 1u));
        s_dA[pos] = dA;
        s_dW[pos] = dW;
    }
    __syncthreads();
    int cnt = s_wcnt[0] + s_wcnt[1] + s_wcnt[2] + s_wcnt[3] + s_wcnt[4] + s_wcnt[5];

    const int g = wrp;
    float acc = 0.f;
#pragma unroll 2
    for (int i = 0; i < cnt; i++) {
        int4 D = s_dA[i];
        float4 wt = s_dW[i];
        const __half* basep = g_nhwc + (((size_t)D.x) << 8) + c;
        float v00 = __half2float(basep[0]);
        float v01 = __half2float(basep[D.y]);
        float v10 = __half2float(basep[D.z]);
        float v11 = __half2float(basep[D.z + D.y]);
        float s = fmaf(wt.x, v00, fmaf(wt.y, v01, fmaf(wt.z, v10, wt.w * v11)));
        acc = fmaf(s, s_w[D.w + g], acc);
    }
    g_fusedT[(size_t)c * NBA + ba] = acc;
}

// =====================================================================
// Out-projection, split-K=4 (fp32 operands).
// =====================================================================
__global__ void __launch_bounds__(256) outproj_splitk(float* __restrict__ P)
{
    __shared__ float As[32][64];
    __shared__ float Bs[32][64];
    const float* AT = g_fusedT;
    const float* BT = g_woutT;
    const int bn0 = blockIdx.x * 64;
    const int bm0 = blockIdx.y * 64;
    const int kz  = blockIdx.z;
    const int tid  = threadIdx.x;
    const int wid  = tid >> 5;
    const int lane = tid & 31;
    const int warpM = wid & 3;
    const int warpN = wid >> 2;
    const int m0 = warpM * 16 + (lane >> 3) * 4;
    const int n0 = warpN * 32 + (lane & 7) * 4;
    const int M = NBA, N = EDD;

    float acc[4][4];
#pragma unroll
    for (int i = 0; i < 4; i++)
#pragma unroll
        for (int j = 0; j < 4; j++) acc[i][j] = 0.f;

    for (int kt = kz * 64; kt < kz * 64 + 64; kt += 32) {
#pragma unroll
        for (int s = 0; s < 2; s++) {
            int id = tid + s * 256;
            int k = id >> 4, mq = id & 15;
            int m = bm0 + mq * 4;
            float4 v = make_float4(0.f, 0.f, 0.f, 0.f);
            if (m < M) v = *(const float4*)(AT + (size_t)(kt + k) * M + m);
            *(float4*)&As[k][mq * 4] = v;
        }
#pragma unroll
        for (int s = 0; s < 2; s++) {
            int id = tid + s * 256;
            int k = id >> 4, nq = id & 15;
            *(float4*)&Bs[k][nq * 4] =
                *(const float4*)(BT + (size_t)(kt + k) * N + bn0 + nq * 4);
        }
        __syncthreads();

#pragma unroll
        for (int k = 0; k < 32; k++) {
            float4 a = *(const float4*)&As[k][m0];
            float4 bq = *(const float4*)&Bs[k][n0];
            float am[4] = {a.x, a.y, a.z, a.w};
            float bv[4] = {bq.x, bq.y, bq.z, bq.w};
#pragma unroll
            for (int i = 0; i < 4; i++)
#pragma unroll
                for (int j = 0; j < 4; j++)
                    acc[i][j] = fmaf(am[i], bv[j], acc[i][j]);
        }
        __syncthreads();
    }

#pragma unroll
    for (int i = 0; i < 4; i++) {
        int m = bm0 + m0 + i;
        if (m >= M) continue;
        float4 o = make_float4(acc[i][0], acc[i][1], acc[i][2], acc[i][3]);
        *(float4*)(P + ((size_t)kz * M + m) * N + bn0 + n0) = o;
    }
}

__global__ void __launch_bounds__(256) reduce_out(
    const float* __restrict__ bias, float* __restrict__ out)
{
    int idx = blockIdx.x * 256 + threadIdx.x;
    if (idx >= NBA * EDD / 4) return;
    int e = idx * 4;
    int col = e & 255;
    const float* P = g_part;
    float4 r0 = *(const float4*)(P + e);
    float4 r1 = *(const float4*)(P + (size_t)NBA * EDD + e);
    float4 r2 = *(const float4*)(P + (size_t)2 * NBA * EDD + e);
    float4 r3 = *(const float4*)(P + (size_t)3 * NBA * EDD + e);
    float4 bb = *(const float4*)(bias + col);
    float4 o;
    o.x = r0.x + r1.x + r2.x + r3.x + bb.x;
    o.y = r0.y + r1.y + r2.y + r3.y + bb.y;
    o.z = r0.z + r1.z + r2.z + r3.z + bb.z;
    o.w = r0.w + r1.w + r2.w + r3.w + bb.w;
    *(float4*)(out + e) = o;
}

// =====================================================================
// launch
// =====================================================================
extern "C" void kernel_launch(void* const* d_in, const int* in_sizes, int n_in,
                              void* d_out, int out_size)
{
    const float* inst   = (const float*)d_in[0];
    const float* anchor = (const float*)d_in[1];
    const float* emb    = (const float*)d_in[2];
    const float* f0     = (const float*)d_in[3];
    const float* f1     = (const float*)d_in[4];
    const float* f2     = (const float*)d_in[5];
    const float* f3     = (const float*)d_in[6];
    const float* proj   = (const float*)d_in[7];
    const float* wh     = (const float*)d_in[8];
    const float* w_fc   = (const float*)d_in[9];
    const float* b_fc   = (const float*)d_in[10];
    const float* w_out  = (const float*)d_in[11];
    const float* b_out  = (const float*)d_in[12];
    float* out = (float*)d_out;

    float *gw, *part;
    cudaGetSymbolAddress((void**)&gw,   g_w);
    cudaGetSymbolAddress((void**)&part, g_part);

    prep_kernel<<<456 + 336 + 64, dim3(32, 8)>>>(inst, emb, w_fc, w_out);
    mega_kernel<<<GEMM_BLKS + CVTOT, 256>>>(b_fc, gw, f0, f1, f2, f3);
    agg_kernel<<<NBA, 256>>>(anchor, proj, wh);
    outproj_splitk<<<dim3(EDD / 64, (NBA + 63) / 64, SPLITK), 256>>>(part);
    reduce_out<<<(NBA * EDD / 4 + 255) / 256, 256>>>(b_out, out);
}

// round 7
// speedup vs baseline: 1.7830x; 1.1530x over previous
#include <cuda_runtime.h>
#include <cuda_fp16.h>
#include <mma.h>
#include <math.h>

using namespace nvcuda;

// ----- problem constants -----
#define BB    2
#define AA    900
#define EDD   256
#define NGRP  8
#define NCAM  6
#define NLVL  4
#define NPT   7
#define NW    1344            // NGRP*NCAM*NLVL*NPT
#define NBA   (BB*AA)         // 1800
#define MPAD  1920            // padded anchors for 128-row wmma tiles
#define NDESC (NCAM*NPT*NLVL) // 168
#define NBC   (BB*NCAM)       // 12

// level geometry
#define HW0 11264
#define HW1 2816
#define HW2 704
#define HW3 176
#define PB0 0
#define PB1 (NBC*HW0)
#define PB2 (PB1 + NBC*HW1)
#define PB3 (PB2 + NBC*HW2)
#define NPIX (PB3 + NBC*HW3)           // 179520

// conversion blocks
#define CT0 176
#define CT1 44
#define CT2 11
#define CT3 3
#define CV0 (NBC*CT0*4)
#define CV1 (NBC*CT1*4)
#define CV2 (NBC*CT2*4)
#define CV3 (NBC*CT3*4)
#define CVTOT (CV0+CV1+CV2+CV3)        // 11232

#define GEMM_BLKS ((NW/64) * (MPAD/128))   // 21*15 = 315
#define SPLITK 4

// ----- scratch (allocation-free: device globals) -----
__device__ __half g_featT[EDD * MPAD];   // fp16 (inst+emb)^T, zero-padded
__device__ __half g_wfcT[EDD * NW];      // fp16 w_fc^T
__device__ float  g_woutT[EDD * EDD];    // fp32 w_out^T
__device__ float  g_w[MPAD * NW];        // fp32 logits (padded rows)
__device__ float  g_fusedT[EDD * NBA];   // fp32 fused^T
__device__ float  g_part[SPLITK * NBA * EDD];
__device__ __half g_nhwc[(size_t)NPIX * EDD];  // fp16 NHWC features

// ----- helpers -----
__device__ __forceinline__ void stv(float* p, float v)  { *p = v; }
__device__ __forceinline__ void stv(__half* p, float v) { *p = __float2half_rn(v); }

// =====================================================================
// Prep: transposes merged.  block (32,8).
//   featT: 8 x 60 = 480 blocks (writes zeros for m in [1800,1920))
//   wfcT : 8 x 42 = 336
//   woutT: 8 x 8  = 64
// =====================================================================
template<typename T>
__device__ __forceinline__ void do_transpose(
    const float* in, const float* in2, T* out, int M, int MLD,
    int bx, int by, bool add2)
{
    __shared__ float t[32][33];
    const int k0 = bx * 32;
    const int m0 = by * 32;
    const int tx = threadIdx.x, ty = threadIdx.y;
#pragma unroll
    for (int j = ty; j < 32; j += 8) {
        int m = m0 + j;
        float v = 0.f;
        if (m < M) {
            v = in[(size_t)m * 256 + k0 + tx];
            if (add2) v += in2[(size_t)m * 256 + k0 + tx];
        }
        t[j][tx] = v;
    }
    __syncthreads();
#pragma unroll
    for (int j = ty; j < 32; j += 8) {
        int m = m0 + tx;
        stv(&out[(size_t)(k0 + j) * MLD + m], t[tx][j]);  // zero-pads m >= M
    }
    __syncthreads();
}

__global__ void __launch_bounds__(256) prep_kernel(
    const float* __restrict__ inst, const float* __restrict__ emb,
    const float* __restrict__ w_fc, const float* __restrict__ w_out)
{
    int bid = blockIdx.x;
    if (bid < 480) {
        do_transpose<__half>(inst, emb, g_featT, NBA, MPAD, bid % 8, bid / 8, true);
    } else if (bid < 480 + 336) {
        bid -= 480;
        do_transpose<__half>(w_fc, 0, g_wfcT, NW, NW, bid % 8, bid / 8, false);
    } else {
        bid -= 480 + 336;
        do_transpose<float>(w_out, 0, g_woutT, EDD, EDD, bid % 8, bid / 8, false);
    }
}

// =====================================================================
// Mega kernel (256 threads/block):
//   blocks [0, GEMM_BLKS): wmma/HMMA FC GEMM (fp16 x fp16 -> fp32)
//   blocks [GEMM_BLKS, +CVTOT): NCHW fp32 -> NHWC fp16 conversion
// =====================================================================
__global__ void __launch_bounds__(256) mega_kernel(
    const float* __restrict__ f0, const float* __restrict__ f1,
    const float* __restrict__ f2, const float* __restrict__ f3)
{
    __shared__ __align__(16) unsigned char smraw[16896];
    const int tid = threadIdx.x;

    if (blockIdx.x < GEMM_BLKS) {
        // ---- tensor-core GEMM: g_w[MPAD][NW] = featT^T @ wfcT -----
        const int gx = blockIdx.x % (NW / 64);       // n tile (64)
        const int gy = blockIdx.x / (NW / 64);       // m tile (128)
        const int wid = tid >> 5;
        const int wm  = wid & 3;                     // 4 warps in m
        const int wn  = wid >> 2;                    // 2 warps in n
        const int m0 = gy * 128 + wm * 32;
        const int n0 = gx * 64  + wn * 32;

        wmma::fragment<wmma::accumulator, 16, 16, 16, float> cf[2][2];
#pragma unroll
        for (int i = 0; i < 2; i++)
#pragma unroll
            for (int j = 0; j < 2; j++) wmma::fill_fragment(cf[i][j], 0.f);

        for (int k0 = 0; k0 < 256; k0 += 16) {
            wmma::fragment<wmma::matrix_a, 16, 16, 16, __half, wmma::col_major> af[2];
            wmma::fragment<wmma::matrix_b, 16, 16, 16, __half, wmma::row_major> bf[2];
#pragma unroll
            for (int i = 0; i < 2; i++)
                wmma::load_matrix_sync(af[i], g_featT + (size_t)k0 * MPAD + m0 + i * 16, MPAD);
#pragma unroll
            for (int j = 0; j < 2; j++)
                wmma::load_matrix_sync(bf[j], g_wfcT + (size_t)k0 * NW + n0 + j * 16, NW);
#pragma unroll
            for (int i = 0; i < 2; i++)
#pragma unroll
                for (int j = 0; j < 2; j++)
                    wmma::mma_sync(cf[i][j], af[i], bf[j], cf[i][j]);
        }
#pragma unroll
        for (int i = 0; i < 2; i++)
#pragma unroll
            for (int j = 0; j < 2; j++)
                wmma::store_matrix_sync(g_w + (size_t)(m0 + i * 16) * NW + n0 + j * 16,
                                        cf[i][j], NW, wmma::mem_row_major);
    } else {
        // ------- NCHW fp32 -> NHWC fp16, 64ch x 64px tile ---------------
        int cb = blockIdx.x - GEMM_BLKS;
        const float* fin; int HWl, tilesHW, pbase;
        if (cb < CV0)               { fin = f0; HWl = HW0; tilesHW = CT0; pbase = PB0; }
        else if ((cb -= CV0) < CV1) { fin = f1; HWl = HW1; tilesHW = CT1; pbase = PB1; }
        else if ((cb -= CV1) < CV2) { fin = f2; HWl = HW2; tilesHW = CT2; pbase = PB2; }
        else       { cb -= CV2;       fin = f3; HWl = HW3; tilesHW = CT3; pbase = PB3; }
        const int nt  = tilesHW * 4;
        const int bc  = cb / nt;
        const int r   = cb % nt;
        const int hw0 = (r >> 2) * 64;
        const int c0  = (r & 3) * 64;
        float (*t)[65] = (float(*)[65])smraw;

        const float* ip = fin + (size_t)bc * 256 * HWl;
#pragma unroll
        for (int s = 0; s < 4; s++) {
            int id = tid + s * 256;
            int row = id >> 4, q = id & 15;
            int hw = hw0 + q * 4;
            if (hw < HWl) {
                float4 v = *(const float4*)(ip + (size_t)(c0 + row) * HWl + hw);
                t[row][q * 4 + 0] = v.x;
                t[row][q * 4 + 1] = v.y;
                t[row][q * 4 + 2] = v.z;
                t[row][q * 4 + 3] = v.w;
            }
        }
        __syncthreads();
        __half* op = g_nhwc + ((size_t)(pbase + bc * HWl)) * 256;
#pragma unroll
        for (int s = 0; s < 4; s++) {
            int id = tid + s * 256;
            int px = id >> 4, qc = id & 15;
            int hw = hw0 + px;
            if (hw < HWl) {
                __half2 h0 = __floats2half2_rn(t[qc * 4 + 0][px], t[qc * 4 + 1][px]);
                __half2 h1 = __floats2half2_rn(t[qc * 4 + 2][px], t[qc * 4 + 3][px]);
                __half2* dst = (__half2*)(op + (size_t)hw * 256 + c0 + qc * 4);
                dst[0] = h0;
                dst[1] = h1;
            }
        }
    }
}

// =====================================================================
// Fused aggregation: 64 threads/block, 4 channels/thread (uint2 gathers)
// =====================================================================
__global__ void __launch_bounds__(64) agg_kernel(
    const float* __restrict__ anchor, const float* __restrict__ proj,
    const float* __restrict__ wh, const float* __restrict__ b_fc)
{
    __shared__ float  s_w[NW];
    __shared__ float  s_uv[NCAM * NPT][2];
    __shared__ int4   s_dA[NDESC];
    __shared__ float4 s_dW[NDESC];
    __shared__ int    s_cnt[6];      // (iter 0..2) x (warp 0..1)

    const int ba   = blockIdx.x;
    const int b    = ba / AA;
    const int tid  = threadIdx.x;    // 0..63
    const int wrp  = tid >> 5;       // 0..1
    const int lane = tid & 31;
    const int g    = tid >> 3;       // group of this thread's 4 channels

    // ---- logits + bias ----
    for (int i = tid; i < NW; i += 64) s_w[i] = g_w[(size_t)ba * NW + i] + b_fc[i];

    // ---- projection of 42 keypoints ----
    if (tid < NCAM * NPT) {
        const float fsx[7] = {0.f, 0.45f, -0.45f, 0.f, 0.f, 0.f, 0.f};
        const float fsy[7] = {0.f, 0.f, 0.f, 0.45f, -0.45f, 0.f, 0.f};
        const float fsz[7] = {0.f, 0.f, 0.f, 0.f, 0.f, 0.45f, -0.45f};
        int cam = tid / NPT, p = tid % NPT;
        const float* an = anchor + (size_t)ba * 8;
        float e0 = expf(an[3]), e1 = expf(an[4]), e2 = expf(an[5]);
        float k0 = fsx[p] * e0, k1 = fsy[p] * e1, k2 = fsz[p] * e2;
        float sn = an[6], cs = an[7];
        float X = cs * k0 - sn * k1 + an[0];
        float Y = sn * k0 + cs * k1 + an[1];
        float Z = k2 + an[2];
        const float* M = proj + (size_t)(b * NCAM + cam) * 16;
        float d0 = M[0] * X + M[1] * Y + M[2]  * Z + M[3];
        float d1 = M[4] * X + M[5] * Y + M[6]  * Z + M[7];
        float d2 = M[8] * X + M[9] * Y + M[10] * Z + M[11];
        float iz = 1.f / fmaxf(d2, 1e-5f);
        float x = d0 * iz / fmaxf(wh[(size_t)(b * NCAM + cam) * 2 + 0], 1e-5f);
        float y = d1 * iz / fmaxf(wh[(size_t)(b * NCAM + cam) * 2 + 1], 1e-5f);
        s_uv[tid][0] = x * 2.f - 1.f;
        s_uv[tid][1] = y * 2.f - 1.f;
    }
    __syncthreads();

    // ---- softmax: warp wrp handles groups wrp*4 .. wrp*4+3 ----
#pragma unroll
    for (int q = 0; q < 4; q++) {
        int gg = wrp * 4 + q;
        float mx = -INFINITY;
        for (int cc = lane; cc < 168; cc += 32) mx = fmaxf(mx, s_w[cc * 8 + gg]);
#pragma unroll
        for (int o = 16; o; o >>= 1) mx = fmaxf(mx, __shfl_xor_sync(0xffffffffu, mx, o));
        float sum = 0.f;
        for (int cc = lane; cc < 168; cc += 32) {
            float e = expf(s_w[cc * 8 + gg] - mx);
            s_w[cc * 8 + gg] = e;
            sum += e;
        }
#pragma unroll
        for (int o = 16; o; o >>= 1) sum += __shfl_xor_sync(0xffffffffu, sum, o);
        float inv = 1.f / sum;
        for (int cc = lane; cc < 168; cc += 32) s_w[cc * 8 + gg] *= inv;
    }

    // ---- descriptors: 168 over 64 threads, 3 iterations ----
    const int Hl[4]  = {64, 32, 16, 8};
    const int Wl[4]  = {176, 88, 44, 22};
    const int HWl[4] = {HW0, HW1, HW2, HW3};
    const int PBl[4] = {PB0, PB1, PB2, PB3};
    int4   dA3[3];
    float4 dW3[3];
    unsigned bal3[3];
    int flags = 0;
#pragma unroll
    for (int it = 0; it < 3; it++) {
        int d = it * 64 + tid;
        int flag = 0;
        if (d < NDESC) {
            int cam = d / (NPT * NLVL);
            int r   = d - cam * (NPT * NLVL);
            int p   = r >> 2;
            int lvl = r & 3;
            float u = s_uv[cam * NPT + p][0];
            float v = s_uv[cam * NPT + p][1];
            const int H = Hl[lvl], W = Wl[lvl];
            float gx = (u + 1.f) * (W * 0.5f) - 0.5f;
            float gy = (v + 1.f) * (H * 0.5f) - 0.5f;
            float x0f = floorf(gx), y0f = floorf(gy);
            float wx1 = gx - x0f, wy1 = gy - y0f;
            bool vx0 = (x0f >= 0.f)       && (x0f <= (float)(W - 1));
            bool vx1 = (x0f + 1.f >= 0.f) && (x0f + 1.f <= (float)(W - 1));
            bool vy0 = (y0f >= 0.f)       && (y0f <= (float)(H - 1));
            bool vy1 = (y0f + 1.f >= 0.f) && (y0f + 1.f <= (float)(H - 1));
            flag = ((vx0 || vx1) && (vy0 || vy1)) ? 1 : 0;
            int x0 = (int)fminf(fmaxf(x0f, 0.f),       (float)(W - 1));
            int x1 = (int)fminf(fmaxf(x0f + 1.f, 0.f), (float)(W - 1));
            int y0 = (int)fminf(fmaxf(y0f, 0.f),       (float)(H - 1));
            int y1 = (int)fminf(fmaxf(y0f + 1.f, 0.f), (float)(H - 1));
            dA3[it].x = PBl[lvl] + (b * NCAM + cam) * HWl[lvl] + y0 * W + x0;
            dA3[it].y = (x1 - x0) * 256;
            dA3[it].z = (y1 - y0) * W * 256;
            dA3[it].w = ((cam * NLVL + lvl) * NPT + p) * NGRP;
            dW3[it].x = (vx0 && vy0) ? (1.f - wx1) * (1.f - wy1) : 0.f;
            dW3[it].y = (vx1 && vy0) ? wx1 * (1.f - wy1)         : 0.f;
            dW3[it].z = (vx0 && vy1) ? (1.f - wx1) * wy1         : 0.f;
            dW3[it].w = (vx1 && vy1) ? wx1 * wy1                 : 0.f;
        }
        bal3[it] = __ballot_sync(0xffffffffu, flag);
        flags |= flag << it;
        if (lane == 0) s_cnt[it * 2 + wrp] = __popc(bal3[it]);
    }
    __syncthreads();

    int pfx[6];
    {
        int run = 0;
#pragma unroll
        for (int i = 0; i < 6; i++) { pfx[i] = run; run += s_cnt[i]; }
    }
    int cnt = pfx[5] + s_cnt[5];
#pragma unroll
    for (int it = 0; it < 3; it++) {
        if ((flags >> it) & 1) {
            int pos = pfx[it * 2 + wrp] + __popc(bal3[it] & ((1u << lane) - 1u));
            s_dA[pos] = dA3[it];
            s_dW[pos] = dW3[it];
        }
    }
    __syncthreads();

    // ---- gather + fuse: each thread handles channels tid*4 .. tid*4+3 ----
    const __half* chan = g_nhwc + tid * 4;
    float acc0 = 0.f, acc1 = 0.f, acc2 = 0.f, acc3 = 0.f;
#pragma unroll 2
    for (int i = 0; i < cnt; i++) {
        int4 D = s_dA[i];
        float4 wt = s_dW[i];
        const __half* bp = chan + (((size_t)D.x) << 8);
        uint2 r00 = *(const uint2*)(bp);
        uint2 r01 = *(const uint2*)(bp + D.y);
        uint2 r10 = *(const uint2*)(bp + D.z);
        uint2 r11 = *(const uint2*)(bp + D.z + D.y);
        float wf = s_w[D.w + g];

        float2 a00 = __half22float2(*(__half2*)&r00.x);
        float2 b00 = __half22float2(*(__half2*)&r00.y);
        float2 a01 = __half22float2(*(__half2*)&r01.x);
        float2 b01 = __half22float2(*(__half2*)&r01.y);
        float2 a10 = __half22float2(*(__half2*)&r10.x);
        float2 b10 = __half22float2(*(__half2*)&r10.y);
        float2 a11 = __half22float2(*(__half2*)&r11.x);
        float2 b11 = __half22float2(*(__half2*)&r11.y);

        float s0 = fmaf(wt.x, a00.x, fmaf(wt.y, a01.x, fmaf(wt.z, a10.x, wt.w * a11.x)));
        float s1 = fmaf(wt.x, a00.y, fmaf(wt.y, a01.y, fmaf(wt.z, a10.y, wt.w * a11.y)));
        float s2 = fmaf(wt.x, b00.x, fmaf(wt.y, b01.x, fmaf(wt.z, b10.x, wt.w * b11.x)));
        float s3 = fmaf(wt.x, b00.y, fmaf(wt.y, b01.y, fmaf(wt.z, b10.y, wt.w * b11.y)));
        acc0 = fmaf(s0, wf, acc0);
        acc1 = fmaf(s1, wf, acc1);
        acc2 = fmaf(s2, wf, acc2);
        acc3 = fmaf(s3, wf, acc3);
    }
    const int c0 = tid * 4;
    g_fusedT[(size_t)(c0 + 0) * NBA + ba] = acc0;
    g_fusedT[(size_t)(c0 + 1) * NBA + ba] = acc1;
    g_fusedT[(size_t)(c0 + 2) * NBA + ba] = acc2;
    g_fusedT[(size_t)(c0 + 3) * NBA + ba] = acc3;
}

// =====================================================================
// Out-projection, split-K=4 (fp32 operands).
// =====================================================================
__global__ void __launch_bounds__(256) outproj_splitk(float* __restrict__ P)
{
    __shared__ float As[32][64];
    __shared__ float Bs[32][64];
    const float* AT = g_fusedT;
    const float* BT = g_woutT;
    const int bn0 = blockIdx.x * 64;
    const int bm0 = blockIdx.y * 64;
    const int kz  = blockIdx.z;
    const int tid  = threadIdx.x;
    const int wid  = tid >> 5;
    const int lane = tid & 31;
    const int warpM = wid & 3;
    const int warpN = wid >> 2;
    const int m0 = warpM * 16 + (lane >> 3) * 4;
    const int n0 = warpN * 32 + (lane & 7) * 4;
    const int M = NBA, N = EDD;

    float acc[4][4];
#pragma unroll
    for (int i = 0; i < 4; i++)
#pragma unroll
        for (int j = 0; j < 4; j++) acc[i][j] = 0.f;

    for (int kt = kz * 64; kt < kz * 64 + 64; kt += 32) {
#pragma unroll
        for (int s = 0; s < 2; s++) {
            int id = tid + s * 256;
            int k = id >> 4, mq = id & 15;
            int m = bm0 + mq * 4;
            float4 v = make_float4(0.f, 0.f, 0.f, 0.f);
            if (m < M) v = *(const float4*)(AT + (size_t)(kt + k) * M + m);
            *(float4*)&As[k][mq * 4] = v;
        }
#pragma unroll
        for (int s = 0; s < 2; s++) {
            int id = tid + s * 256;
            int k = id >> 4, nq = id & 15;
            *(float4*)&Bs[k][nq * 4] =
                *(const float4*)(BT + (size_t)(kt + k) * N + bn0 + nq * 4);
        }
        __syncthreads();

#pragma unroll
        for (int k = 0; k < 32; k++) {
            float4 a = *(const float4*)&As[k][m0];
            float4 bq = *(const float4*)&Bs[k][n0];
            float am[4] = {a.x, a.y, a.z, a.w};
            float bv[4] = {bq.x, bq.y, bq.z, bq.w};
#pragma unroll
            for (int i = 0; i < 4; i++)
#pragma unroll
                for (int j = 0; j < 4; j++)
                    acc[i][j] = fmaf(am[i], bv[j], acc[i][j]);
        }
        __syncthreads();
    }

#pragma unroll
    for (int i = 0; i < 4; i++) {
        int m = bm0 + m0 + i;
        if (m >= M) continue;
        float4 o = make_float4(acc[i][0], acc[i][1], acc[i][2], acc[i][3]);
        *(float4*)(P + ((size_t)kz * M + m) * N + bn0 + n0) = o;
    }
}

__global__ void __launch_bounds__(256) reduce_out(
    const float* __restrict__ bias, float* __restrict__ out)
{
    int idx = blockIdx.x * 256 + threadIdx.x;
    if (idx >= NBA * EDD / 4) return;
    int e = idx * 4;
    int col = e & 255;
    const float* P = g_part;
    float4 r0 = *(const float4*)(P + e);
    float4 r1 = *(const float4*)(P + (size_t)NBA * EDD + e);
    float4 r2 = *(const float4*)(P + (size_t)2 * NBA * EDD + e);
    float4 r3 = *(const float4*)(P + (size_t)3 * NBA * EDD + e);
    float4 bb = *(const float4*)(bias + col);
    float4 o;
    o.x = r0.x + r1.x + r2.x + r3.x + bb.x;
    o.y = r0.y + r1.y + r2.y + r3.y + bb.y;
    o.z = r0.z + r1.z + r2.z + r3.z + bb.z;
    o.w = r0.w + r1.w + r2.w + r3.w + bb.w;
    *(float4*)(out + e) = o;
}

// =====================================================================
// launch
// =====================================================================
extern "C" void kernel_launch(void* const* d_in, const int* in_sizes, int n_in,
                              void* d_out, int out_size)
{
    const float* inst   = (const float*)d_in[0];
    const float* anchor = (const float*)d_in[1];
    const float* emb    = (const float*)d_in[2];
    const float* f0     = (const float*)d_in[3];
    const float* f1     = (const float*)d_in[4];
    const float* f2     = (const float*)d_in[5];
    const float* f3     = (const float*)d_in[6];
    const float* proj   = (const float*)d_in[7];
    const float* wh     = (const float*)d_in[8];
    const float* w_fc   = (const float*)d_in[9];
    const float* b_fc   = (const float*)d_in[10];
    const float* w_out  = (const float*)d_in[11];
    const float* b_out  = (const float*)d_in[12];
    float* out = (float*)d_out;

    float* part;
    cudaGetSymbolAddress((void**)&part, g_part);

    prep_kernel<<<480 + 336 + 64, dim3(32, 8)>>>(inst, emb, w_fc, w_out);
    mega_kernel<<<GEMM_BLKS + CVTOT, 256>>>(f0, f1, f2, f3);
    agg_kernel<<<NBA, 64>>>(anchor, proj, wh, b_fc);
    outproj_splitk<<<dim3(EDD / 64, (NBA + 63) / 64, SPLITK), 256>>>(part);
    reduce_out<<<(NBA * EDD / 4 + 255) / 256, 256>>>(b_out, out);
}

// round 8
// speedup vs baseline: 1.9765x; 1.1086x over previous
#include <cuda_runtime.h>
#include <cuda_fp16.h>
#include <mma.h>
#include <math.h>

using namespace nvcuda;

// ----- problem constants -----
#define BB    2
#define AA    900
#define EDD   256
#define NGRP  8
#define NCAM  6
#define NLVL  4
#define NPT   7
#define NW    1344            // NGRP*NCAM*NLVL*NPT
#define NBA   (BB*AA)         // 1800
#define MPAD  1920            // padded anchors for wmma tiles
#define NDESC (NCAM*NPT*NLVL) // 168
#define NBC   (BB*NCAM)       // 12

// level geometry
#define HW0 11264
#define HW1 2816
#define HW2 704
#define HW3 176
#define PB0 0
#define PB1 (NBC*HW0)
#define PB2 (PB1 + NBC*HW1)
#define PB3 (PB2 + NBC*HW2)
#define NPIX (PB3 + NBC*HW3)           // 179520

// conversion blocks
#define CT0 176
#define CT1 44
#define CT2 11
#define CT3 3
#define CV0 (NBC*CT0*4)
#define CV1 (NBC*CT1*4)
#define CV2 (NBC*CT2*4)
#define CV3 (NBC*CT3*4)
#define CVTOT (CV0+CV1+CV2+CV3)        // 11232

#define GEMM_BLKS ((NW/64) * (MPAD/128))   // 315

// elementwise prep ranges (in float4 units)
#define N_FEAT4 (NBA*EDD/4)            // 115200
#define N_WFC4  (NW*EDD/4)             // 86016
#define N_WOUT4 (EDD*EDD/4)            // 16384
#define N_PREP4 (N_FEAT4+N_WFC4+N_WOUT4)

// ----- scratch (allocation-free: device globals; zero-initialized) -----
__device__ __half g_featH[MPAD * EDD];   // fp16 (inst+emb), row-major, zero-pad
__device__ __half g_wfcH[NW * EDD];      // fp16 w_fc  [N][K] (= col-major B)
__device__ __half g_woutH[EDD * EDD];    // fp16 w_out [N][K]
__device__ float  g_w[MPAD * NW];        // fp32 logits
__device__ __half g_fusedH[MPAD * EDD];  // fp16 fused, row-major, zero-pad
__device__ __half g_nhwc[(size_t)NPIX * EDD];  // fp16 NHWC features

// =====================================================================
// Prep: pure elementwise fp32 -> fp16 conversion (no transposes).
// =====================================================================
__global__ void __launch_bounds__(256) prep_kernel(
    const float* __restrict__ inst, const float* __restrict__ emb,
    const float* __restrict__ w_fc, const float* __restrict__ w_out)
{
    int i = blockIdx.x * 256 + threadIdx.x;     // float4 index
    const float* src; const float* src2 = 0; __half* dst; int base;
    if (i < N_FEAT4) {
        src = inst; src2 = emb; dst = g_featH; base = 0;
    } else if (i < N_FEAT4 + N_WFC4) {
        src = w_fc; dst = g_wfcH; base = N_FEAT4; 
    } else if (i < N_PREP4) {
        src = w_out; dst = g_woutH; base = N_FEAT4 + N_WFC4;
    } else return;
    int j = i - base;
    float4 v = *(const float4*)(src + (size_t)j * 4);
    if (src2) {
        float4 w = *(const float4*)(src2 + (size_t)j * 4);
        v.x += w.x; v.y += w.y; v.z += w.z; v.w += w.w;
    }
    __half2* d = (__half2*)(dst + (size_t)j * 4);
    d[0] = __floats2half2_rn(v.x, v.y);
    d[1] = __floats2half2_rn(v.z, v.w);
}

// =====================================================================
// Mega kernel (256 threads/block):
//   blocks [0, GEMM_BLKS): wmma FC GEMM  (A row-major, B col-major)
//   blocks [GEMM_BLKS, +CVTOT): NCHW fp32 -> NHWC fp16 (__ldcs reads)
// =====================================================================
__global__ void __launch_bounds__(256) mega_kernel(
    const float* __restrict__ f0, const float* __restrict__ f1,
    const float* __restrict__ f2, const float* __restrict__ f3)
{
    __shared__ __align__(16) unsigned char smraw[16896];
    const int tid = threadIdx.x;

    if (blockIdx.x < GEMM_BLKS) {
        const int gx = blockIdx.x % (NW / 64);
        const int gy = blockIdx.x / (NW / 64);
        const int wid = tid >> 5;
        const int wm  = wid & 3;
        const int wn  = wid >> 2;
        const int m0 = gy * 128 + wm * 32;
        const int n0 = gx * 64  + wn * 32;

        wmma::fragment<wmma::accumulator, 16, 16, 16, float> cf[2][2];
#pragma unroll
        for (int i = 0; i < 2; i++)
#pragma unroll
            for (int j = 0; j < 2; j++) wmma::fill_fragment(cf[i][j], 0.f);

        for (int k0 = 0; k0 < 256; k0 += 16) {
            wmma::fragment<wmma::matrix_a, 16, 16, 16, __half, wmma::row_major> af[2];
            wmma::fragment<wmma::matrix_b, 16, 16, 16, __half, wmma::col_major> bf[2];
#pragma unroll
            for (int i = 0; i < 2; i++)
                wmma::load_matrix_sync(af[i], g_featH + (size_t)(m0 + i * 16) * EDD + k0, EDD);
#pragma unroll
            for (int j = 0; j < 2; j++)
                wmma::load_matrix_sync(bf[j], g_wfcH + (size_t)(n0 + j * 16) * EDD + k0, EDD);
#pragma unroll
            for (int i = 0; i < 2; i++)
#pragma unroll
                for (int j = 0; j < 2; j++)
                    wmma::mma_sync(cf[i][j], af[i], bf[j], cf[i][j]);
        }
#pragma unroll
        for (int i = 0; i < 2; i++)
#pragma unroll
            for (int j = 0; j < 2; j++)
                wmma::store_matrix_sync(g_w + (size_t)(m0 + i * 16) * NW + n0 + j * 16,
                                        cf[i][j], NW, wmma::mem_row_major);
    } else {
        // ------- NCHW fp32 -> NHWC fp16, 64ch x 64px tile ---------------
        int cb = blockIdx.x - GEMM_BLKS;
        const float* fin; int HWl, tilesHW, pbase;
        if (cb < CV0)               { fin = f0; HWl = HW0; tilesHW = CT0; pbase = PB0; }
        else if ((cb -= CV0) < CV1) { fin = f1; HWl = HW1; tilesHW = CT1; pbase = PB1; }
        else if ((cb -= CV1) < CV2) { fin = f2; HWl = HW2; tilesHW = CT2; pbase = PB2; }
        else       { cb -= CV2;       fin = f3; HWl = HW3; tilesHW = CT3; pbase = PB3; }
        const int nt  = tilesHW * 4;
        const int bc  = cb / nt;
        const int r   = cb % nt;
        const int hw0 = (r >> 2) * 64;
        const int c0  = (r & 3) * 64;
        float (*t)[65] = (float(*)[65])smraw;

        const float* ip = fin + (size_t)bc * 256 * HWl;
#pragma unroll
        for (int s = 0; s < 4; s++) {
            int id = tid + s * 256;
            int row = id >> 4, q = id & 15;
            int hw = hw0 + q * 4;
            if (hw < HWl) {
                float4 v = __ldcs((const float4*)(ip + (size_t)(c0 + row) * HWl + hw));
                t[row][q * 4 + 0] = v.x;
                t[row][q * 4 + 1] = v.y;
                t[row][q * 4 + 2] = v.z;
                t[row][q * 4 + 3] = v.w;
            }
        }
        __syncthreads();
        __half* op = g_nhwc + ((size_t)(pbase + bc * HWl)) * 256;
#pragma unroll
        for (int s = 0; s < 4; s++) {
            int id = tid + s * 256;
            int px = id >> 4, qc = id & 15;
            int hw = hw0 + px;
            if (hw < HWl) {
                __half2 h0 = __floats2half2_rn(t[qc * 4 + 0][px], t[qc * 4 + 1][px]);
                __half2 h1 = __floats2half2_rn(t[qc * 4 + 2][px], t[qc * 4 + 3][px]);
                __half2* dst = (__half2*)(op + (size_t)hw * 256 + c0 + qc * 4);
                dst[0] = h0;
                dst[1] = h1;
            }
        }
    }
}

// =====================================================================
// Fused aggregation: 64 threads/block, 4 channels/thread (uint2 gathers).
// Writes fused row-major fp16 (contiguous per anchor).
// =====================================================================
__global__ void __launch_bounds__(64) agg_kernel(
    const float* __restrict__ anchor, const float* __restrict__ proj,
    const float* __restrict__ wh, const float* __restrict__ b_fc)
{
    __shared__ float  s_w[NW];
    __shared__ float  s_uv[NCAM * NPT][2];
    __shared__ int4   s_dA[NDESC];
    __shared__ float4 s_dW[NDESC];
    __shared__ int    s_cnt[6];

    const int ba   = blockIdx.x;
    const int b    = ba / AA;
    const int tid  = threadIdx.x;
    const int wrp  = tid >> 5;
    const int lane = tid & 31;
    const int g    = tid >> 3;

    for (int i = tid; i < NW; i += 64) s_w[i] = g_w[(size_t)ba * NW + i] + b_fc[i];

    if (tid < NCAM * NPT) {
        const float fsx[7] = {0.f, 0.45f, -0.45f, 0.f, 0.f, 0.f, 0.f};
        const float fsy[7] = {0.f, 0.f, 0.f, 0.45f, -0.45f, 0.f, 0.f};
        const float fsz[7] = {0.f, 0.f, 0.f, 0.f, 0.f, 0.45f, -0.45f};
        int cam = tid / NPT, p = tid % NPT;
        const float* an = anchor + (size_t)ba * 8;
        float e0 = expf(an[3]), e1 = expf(an[4]), e2 = expf(an[5]);
        float k0 = fsx[p] * e0, k1 = fsy[p] * e1, k2 = fsz[p] * e2;
        float sn = an[6], cs = an[7];
        float X = cs * k0 - sn * k1 + an[0];
        float Y = sn * k0 + cs * k1 + an[1];
        float Z = k2 + an[2];
        const float* M = proj + (size_t)(b * NCAM + cam) * 16;
        float d0 = M[0] * X + M[1] * Y + M[2]  * Z + M[3];
        float d1 = M[4] * X + M[5] * Y + M[6]  * Z + M[7];
        float d2 = M[8] * X + M[9] * Y + M[10] * Z + M[11];
        float iz = 1.f / fmaxf(d2, 1e-5f);
        float x = d0 * iz / fmaxf(wh[(size_t)(b * NCAM + cam) * 2 + 0], 1e-5f);
        float y = d1 * iz / fmaxf(wh[(size_t)(b * NCAM + cam) * 2 + 1], 1e-5f);
        s_uv[tid][0] = x * 2.f - 1.f;
        s_uv[tid][1] = y * 2.f - 1.f;
    }
    __syncthreads();

#pragma unroll
    for (int q = 0; q < 4; q++) {
        int gg = wrp * 4 + q;
        float mx = -INFINITY;
        for (int cc = lane; cc < 168; cc += 32) mx = fmaxf(mx, s_w[cc * 8 + gg]);
#pragma unroll
        for (int o = 16; o; o >>= 1) mx = fmaxf(mx, __shfl_xor_sync(0xffffffffu, mx, o));
        float sum = 0.f;
        for (int cc = lane; cc < 168; cc += 32) {
            float e = expf(s_w[cc * 8 + gg] - mx);
            s_w[cc * 8 + gg] = e;
            sum += e;
        }
#pragma unroll
        for (int o = 16; o; o >>= 1) sum += __shfl_xor_sync(0xffffffffu, sum, o);
        float inv = 1.f / sum;
        for (int cc = lane; cc < 168; cc += 32) s_w[cc * 8 + gg] *= inv;
    }

    const int Hl[4]  = {64, 32, 16, 8};
    const int Wl[4]  = {176, 88, 44, 22};
    const int HWl[4] = {HW0, HW1, HW2, HW3};
    const int PBl[4] = {PB0, PB1, PB2, PB3};
    int4   dA3[3];
    float4 dW3[3];
    unsigned bal3[3];
    int flags = 0;
#pragma unroll
    for (int it = 0; it < 3; it++) {
        int d = it * 64 + tid;
        int flag = 0;
        if (d < NDESC) {
            int cam = d / (NPT * NLVL);
            int r   = d - cam * (NPT * NLVL);
            int p   = r >> 2;
            int lvl = r & 3;
            float u = s_uv[cam * NPT + p][0];
            float v = s_uv[cam * NPT + p][1];
            const int H = Hl[lvl], W = Wl[lvl];
            float gx = (u + 1.f) * (W * 0.5f) - 0.5f;
            float gy = (v + 1.f) * (H * 0.5f) - 0.5f;
            float x0f = floorf(gx), y0f = floorf(gy);
            float wx1 = gx - x0f, wy1 = gy - y0f;
            bool vx0 = (x0f >= 0.f)       && (x0f <= (float)(W - 1));
            bool vx1 = (x0f + 1.f >= 0.f) && (x0f + 1.f <= (float)(W - 1));
            bool vy0 = (y0f >= 0.f)       && (y0f <= (float)(H - 1));
            bool vy1 = (y0f + 1.f >= 0.f) && (y0f + 1.f <= (float)(H - 1));
            flag = ((vx0 || vx1) && (vy0 || vy1)) ? 1 : 0;
            int x0 = (int)fminf(fmaxf(x0f, 0.f),       (float)(W - 1));
            int x1 = (int)fminf(fmaxf(x0f + 1.f, 0.f), (float)(W - 1));
            int y0 = (int)fminf(fmaxf(y0f, 0.f),       (float)(H - 1));
            int y1 = (int)fminf(fmaxf(y0f + 1.f, 0.f), (float)(H - 1));
            dA3[it].x = PBl[lvl] + (b * NCAM + cam) * HWl[lvl] + y0 * W + x0;
            dA3[it].y = (x1 - x0) * 256;
            dA3[it].z = (y1 - y0) * W * 256;
            dA3[it].w = ((cam * NLVL + lvl) * NPT + p) * NGRP;
            dW3[it].x = (vx0 && vy0) ? (1.f - wx1) * (1.f - wy1) : 0.f;
            dW3[it].y = (vx1 && vy0) ? wx1 * (1.f - wy1)         : 0.f;
            dW3[it].z = (vx0 && vy1) ? (1.f - wx1) * wy1         : 0.f;
            dW3[it].w = (vx1 && vy1) ? wx1 * wy1                 : 0.f;
        }
        bal3[it] = __ballot_sync(0xffffffffu, flag);
        flags |= flag << it;
        if (lane == 0) s_cnt[it * 2 + wrp] = __popc(bal3[it]);
    }
    __syncthreads();

    int pfx[6];
    {
        int run = 0;
#pragma unroll
        for (int i = 0; i < 6; i++) { pfx[i] = run; run += s_cnt[i]; }
    }
    int cnt = pfx[5] + s_cnt[5];
#pragma unroll
    for (int it = 0; it < 3; it++) {
        if ((flags >> it) & 1) {
            int pos = pfx[it * 2 + wrp] + __popc(bal3[it] & ((1u << lane) - 1u));
            s_dA[pos] = dA3[it];
            s_dW[pos] = dW3[it];
        }
    }
    __syncthreads();

    const __half* chan = g_nhwc + tid * 4;
    float acc0 = 0.f, acc1 = 0.f, acc2 = 0.f, acc3 = 0.f;
#pragma unroll 2
    for (int i = 0; i < cnt; i++) {
        int4 D = s_dA[i];
        float4 wt = s_dW[i];
        const __half* bp = chan + (((size_t)D.x) << 8);
        uint2 r00 = *(const uint2*)(bp);
        uint2 r01 = *(const uint2*)(bp + D.y);
        uint2 r10 = *(const uint2*)(bp + D.z);
        uint2 r11 = *(const uint2*)(bp + D.z + D.y);
        float wf = s_w[D.w + g];

        float2 a00 = __half22float2(*(__half2*)&r00.x);
        float2 b00 = __half22float2(*(__half2*)&r00.y);
        float2 a01 = __half22float2(*(__half2*)&r01.x);
        float2 b01 = __half22float2(*(__half2*)&r01.y);
        float2 a10 = __half22float2(*(__half2*)&r10.x);
        float2 b10 = __half22float2(*(__half2*)&r10.y);
        float2 a11 = __half22float2(*(__half2*)&r11.x);
        float2 b11 = __half22float2(*(__half2*)&r11.y);

        float s0 = fmaf(wt.x, a00.x, fmaf(wt.y, a01.x, fmaf(wt.z, a10.x, wt.w * a11.x)));
        float s1 = fmaf(wt.x, a00.y, fmaf(wt.y, a01.y, fmaf(wt.z, a10.y, wt.w * a11.y)));
        float s2 = fmaf(wt.x, b00.x, fmaf(wt.y, b01.x, fmaf(wt.z, b10.x, wt.w * b11.x)));
        float s3 = fmaf(wt.x, b00.y, fmaf(wt.y, b01.y, fmaf(wt.z, b10.y, wt.w * b11.y)));
        acc0 = fmaf(s0, wf, acc0);
        acc1 = fmaf(s1, wf, acc1);
        acc2 = fmaf(s2, wf, acc2);
        acc3 = fmaf(s3, wf, acc3);
    }
    // row-major fp16 store (contiguous per anchor)
    __half2* fp = (__half2*)(g_fusedH + (size_t)ba * EDD + tid * 4);
    fp[0] = __floats2half2_rn(acc0, acc1);
    fp[1] = __floats2half2_rn(acc2, acc3);
}

// =====================================================================
// Out-projection wmma: out[M][256] = fusedH @ woutH^T + b_out
// 64x64 tiles, 128 threads (4 warps of 32x32).
// =====================================================================
__global__ void __launch_bounds__(128) outproj_wmma(
    const float* __restrict__ bias, float* __restrict__ out)
{
    __shared__ __align__(16) float sm[64][72];
    const int bx = blockIdx.x;                 // n tile (4)
    const int by = blockIdx.y;                 // m tile (30)
    const int tid = threadIdx.x;
    const int wid = tid >> 5;
    const int wm  = wid >> 1;
    const int wn  = wid & 1;
    const int m0 = by * 64 + wm * 32;
    const int n0 = bx * 64 + wn * 32;

    wmma::fragment<wmma::accumulator, 16, 16, 16, float> cf[2][2];
#pragma unroll
    for (int i = 0; i < 2; i++)
#pragma unroll
        for (int j = 0; j < 2; j++) wmma::fill_fragment(cf[i][j], 0.f);

    for (int k0 = 0; k0 < 256; k0 += 16) {
        wmma::fragment<wmma::matrix_a, 16, 16, 16, __half, wmma::row_major> af[2];
        wmma::fragment<wmma::matrix_b, 16, 16, 16, __half, wmma::col_major> bf[2];
#pragma unroll
        for (int i = 0; i < 2; i++)
            wmma::load_matrix_sync(af[i], g_fusedH + (size_t)(m0 + i * 16) * EDD + k0, EDD);
#pragma unroll
        for (int j = 0; j < 2; j++)
            wmma::load_matrix_sync(bf[j], g_woutH + (size_t)(n0 + j * 16) * EDD + k0, EDD);
#pragma unroll
        for (int i = 0; i < 2; i++)
#pragma unroll
            for (int j = 0; j < 2; j++)
                wmma::mma_sync(cf[i][j], af[i], bf[j], cf[i][j]);
    }
#pragma unroll
    for (int i = 0; i < 2; i++)
#pragma unroll
        for (int j = 0; j < 2; j++)
            wmma::store_matrix_sync(&sm[wm * 32 + i * 16][wn * 32 + j * 16],
                                    cf[i][j], 72, wmma::mem_row_major);
    __syncthreads();

    // epilogue: add bias, write rows m < NBA
    const int c = (tid & 15) * 4;
    float4 bb = *(const float4*)(bias + bx * 64 + c);
    for (int r = (tid >> 4); r < 64; r += 8) {
        int m = by * 64 + r;
        if (m >= NBA) break;
        float4 o;
        o.x = sm[r][c + 0] + bb.x;
        o.y = sm[r][c + 1] + bb.y;
        o.z = sm[r][c + 2] + bb.z;
        o.w = sm[r][c + 3] + bb.w;
        *(float4*)(out + (size_t)m * EDD + bx * 64 + c) = o;
    }
}

// =====================================================================
// launch
// =====================================================================
extern "C" void kernel_launch(void* const* d_in, const int* in_sizes, int n_in,
                              void* d_out, int out_size)
{
    const float* inst   = (const float*)d_in[0];
    const float* anchor = (const float*)d_in[1];
    const float* emb    = (const float*)d_in[2];
    const float* f0     = (const float*)d_in[3];
    const float* f1     = (const float*)d_in[4];
    const float* f2     = (const float*)d_in[5];
    const float* f3     = (const float*)d_in[6];
    const float* proj   = (const float*)d_in[7];
    const float* wh     = (const float*)d_in[8];
    const float* w_fc   = (const float*)d_in[9];
    const float* b_fc   = (const float*)d_in[10];
    const float* w_out  = (const float*)d_in[11];
    const float* b_out  = (const float*)d_in[12];
    float* out = (float*)d_out;

    prep_kernel<<<(N_PREP4 + 255) / 256, 256>>>(inst, emb, w_fc, w_out);
    mega_kernel<<<GEMM_BLKS + CVTOT, 256>>>(f0, f1, f2, f3);
    agg_kernel<<<NBA, 64>>>(anchor, proj, wh, b_fc);
    outproj_wmma<<<dim3(EDD / 64, MPAD / 64), 128>>>(b_out, out);
}

// round 9
// speedup vs baseline: 1.9847x; 1.0041x over previous
#include <cuda_runtime.h>
#include <cuda_fp16.h>
#include <mma.h>
#include <math.h>

using namespace nvcuda;

// ----- problem constants -----
#define BB    2
#define AA    900
#define EDD   256
#define NGRP  8
#define NCAM  6
#define NLVL  4
#define NPT   7
#define NW    1344            // NGRP*NCAM*NLVL*NPT
#define NBA   (BB*AA)         // 1800
#define MPAD  1920
#define NDESC (NCAM*NPT*NLVL) // 168
#define NBC   (BB*NCAM)       // 12

// level geometry
#define HW0 11264
#define HW1 2816
#define HW2 704
#define HW3 176
#define PB0 0
#define PB1 (NBC*HW0)
#define PB2 (PB1 + NBC*HW1)
#define PB3 (PB2 + NBC*HW2)
#define NPIX (PB3 + NBC*HW3)           // 179520

// conversion blocks
#define CT0 176
#define CT1 44
#define CT2 11
#define CT3 3
#define CV0 (NBC*CT0*4)
#define CV1 (NBC*CT1*4)
#define CV2 (NBC*CT2*4)
#define CV3 (NBC*CT3*4)
#define CVTOT (CV0+CV1+CV2+CV3)        // 11232

#define GEMM_BLKS ((NW/64) * (MPAD/128))   // 315
#define WOUT_BLKS 64                       // w_out fp32->fp16, 16384 float4

// ----- scratch (allocation-free: device globals; zero-initialized) -----
__device__ __align__(16) __half g_woutH[EDD * EDD];
__device__ __align__(16) float  g_w[MPAD * NW];
__device__ __align__(16) __half g_fusedH[MPAD * EDD];
__device__ __align__(16) __half g_nhwc[(size_t)NPIX * EDD];

// =====================================================================
// Mega kernel (256 threads/block):
//   [0, GEMM_BLKS): wmma FC GEMM with in-kernel fp32->fp16 staging
//   [GEMM_BLKS, +CVTOT): NCHW fp32 -> NHWC fp16 conversion
//   [+CVTOT, +WOUT_BLKS): w_out fp32 -> fp16 elementwise
// =====================================================================
__global__ void __launch_bounds__(256) mega_kernel(
    const float* __restrict__ inst, const float* __restrict__ emb,
    const float* __restrict__ w_fc, const float* __restrict__ w_out,
    const float* __restrict__ f0, const float* __restrict__ f1,
    const float* __restrict__ f2, const float* __restrict__ f3)
{
    __shared__ __align__(16) unsigned char smraw[16896];
    const int tid = threadIdx.x;

    if (blockIdx.x < GEMM_BLKS) {
        // ---- FC GEMM: g_w[MPAD][NW] = (inst+emb) @ w_fc^T (fp16 compute)
        __half* sA = (__half*)smraw;            // [128][32]  8KB
        __half* sB = (__half*)(smraw + 8192);   // [64][32]   4KB
        const int gx = blockIdx.x % (NW / 64);
        const int gy = blockIdx.x / (NW / 64);
        const int bm0 = gy * 128;
        const int bn0 = gx * 64;
        const int wid = tid >> 5;
        const int wm  = wid & 3;
        const int wn  = wid >> 2;
        const int m0 = wm * 32;
        const int n0 = wn * 32;

        wmma::fragment<wmma::accumulator, 16, 16, 16, float> cf[2][2];
#pragma unroll
        for (int i = 0; i < 2; i++)
#pragma unroll
            for (int j = 0; j < 2; j++) wmma::fill_fragment(cf[i][j], 0.f);

        for (int kt = 0; kt < 256; kt += 32) {
            // stage A tile: 128 rows x 32 k, fp32 -> fp16
#pragma unroll
            for (int s = 0; s < 4; s++) {
                int id = tid + s * 256;         // 0..1023
                int row = id >> 3, q = id & 7;
                int m = bm0 + row;
                float4 v = make_float4(0.f, 0.f, 0.f, 0.f);
                if (m < NBA) {
                    v = *(const float4*)(inst + (size_t)m * 256 + kt + q * 4);
                    float4 w = *(const float4*)(emb + (size_t)m * 256 + kt + q * 4);
                    v.x += w.x; v.y += w.y; v.z += w.z; v.w += w.w;
                }
                __half2* d = (__half2*)&sA[row * 32 + q * 4];
                d[0] = __floats2half2_rn(v.x, v.y);
                d[1] = __floats2half2_rn(v.z, v.w);
            }
            // stage B tile: 64 rows (n) x 32 k
#pragma unroll
            for (int s = 0; s < 2; s++) {
                int id = tid + s * 256;         // 0..511
                int row = id >> 3, q = id & 7;
                int n = bn0 + row;
                float4 v = *(const float4*)(w_fc + (size_t)n * 256 + kt + q * 4);
                __half2* d = (__half2*)&sB[row * 32 + q * 4];
                d[0] = __floats2half2_rn(v.x, v.y);
                d[1] = __floats2half2_rn(v.z, v.w);
            }
            __syncthreads();

#pragma unroll
            for (int kk = 0; kk < 2; kk++) {
                wmma::fragment<wmma::matrix_a, 16, 16, 16, __half, wmma::row_major> af[2];
                wmma::fragment<wmma::matrix_b, 16, 16, 16, __half, wmma::col_major> bf[2];
#pragma unroll
                for (int i = 0; i < 2; i++)
                    wmma::load_matrix_sync(af[i], sA + (m0 + i * 16) * 32 + kk * 16, 32);
#pragma unroll
                for (int j = 0; j < 2; j++)
                    wmma::load_matrix_sync(bf[j], sB + (n0 + j * 16) * 32 + kk * 16, 32);
#pragma unroll
                for (int i = 0; i < 2; i++)
#pragma unroll
                    for (int j = 0; j < 2; j++)
                        wmma::mma_sync(cf[i][j], af[i], bf[j], cf[i][j]);
            }
            __syncthreads();
        }
#pragma unroll
        for (int i = 0; i < 2; i++)
#pragma unroll
            for (int j = 0; j < 2; j++)
                wmma::store_matrix_sync(g_w + (size_t)(bm0 + m0 + i * 16) * NW + bn0 + n0 + j * 16,
                                        cf[i][j], NW, wmma::mem_row_major);
    } else if (blockIdx.x < GEMM_BLKS + CVTOT) {
        // ------- NCHW fp32 -> NHWC fp16, 64ch x 64px tile ---------------
        int cb = blockIdx.x - GEMM_BLKS;
        const float* fin; int HWl, tilesHW, pbase;
        if (cb < CV0)               { fin = f0; HWl = HW0; tilesHW = CT0; pbase = PB0; }
        else if ((cb -= CV0) < CV1) { fin = f1; HWl = HW1; tilesHW = CT1; pbase = PB1; }
        else if ((cb -= CV1) < CV2) { fin = f2; HWl = HW2; tilesHW = CT2; pbase = PB2; }
        else       { cb -= CV2;       fin = f3; HWl = HW3; tilesHW = CT3; pbase = PB3; }
        const int nt  = tilesHW * 4;
        const int bc  = cb / nt;
        const int r   = cb % nt;
        const int hw0 = (r >> 2) * 64;
        const int c0  = (r & 3) * 64;
        float (*t)[65] = (float(*)[65])smraw;

        const float* ip = fin + (size_t)bc * 256 * HWl;
#pragma unroll
        for (int s = 0; s < 4; s++) {
            int id = tid + s * 256;
            int row = id >> 4, q = id & 15;
            int hw = hw0 + q * 4;
            if (hw < HWl) {
                float4 v = __ldcs((const float4*)(ip + (size_t)(c0 + row) * HWl + hw));
                t[row][q * 4 + 0] = v.x;
                t[row][q * 4 + 1] = v.y;
                t[row][q * 4 + 2] = v.z;
                t[row][q * 4 + 3] = v.w;
            }
        }
        __syncthreads();
        __half* op = g_nhwc + ((size_t)(pbase + bc * HWl)) * 256;
#pragma unroll
        for (int s = 0; s < 4; s++) {
            int id = tid + s * 256;
            int px = id >> 4, qc = id & 15;
            int hw = hw0 + px;
            if (hw < HWl) {
                __half2 h0 = __floats2half2_rn(t[qc * 4 + 0][px], t[qc * 4 + 1][px]);
                __half2 h1 = __floats2half2_rn(t[qc * 4 + 2][px], t[qc * 4 + 3][px]);
                __half2* dst = (__half2*)(op + (size_t)hw * 256 + c0 + qc * 4);
                dst[0] = h0;
                dst[1] = h1;
            }
        }
    } else {
        // ------- w_out fp32 -> fp16 -------------------------------------
        int j = (blockIdx.x - GEMM_BLKS - CVTOT) * 256 + tid;   // float4 idx
        float4 v = *(const float4*)(w_out + (size_t)j * 4);
        __half2* d = (__half2*)(g_woutH + (size_t)j * 4);
        d[0] = __floats2half2_rn(v.x, v.y);
        d[1] = __floats2half2_rn(v.z, v.w);
    }
}

// =====================================================================
// Fused aggregation: 64 threads; each thread covers 8 channels (uint4
// gathers); the two warps split the descriptor list (evens/odds).
// =====================================================================
__global__ void __launch_bounds__(64) agg_kernel(
    const float* __restrict__ anchor, const float* __restrict__ proj,
    const float* __restrict__ wh, const float* __restrict__ b_fc)
{
    __shared__ float  s_w[NW];
    __shared__ float  s_uv[NCAM * NPT][2];
    __shared__ int4   s_dA[NDESC];
    __shared__ float4 s_dW[NDESC];
    __shared__ int    s_cnt[6];
    __shared__ float  s_acc[2][EDD];

    const int ba   = blockIdx.x;
    const int b    = ba / AA;
    const int tid  = threadIdx.x;
    const int wrp  = tid >> 5;
    const int lane = tid & 31;

    for (int i = tid; i < NW; i += 64) s_w[i] = g_w[(size_t)ba * NW + i] + b_fc[i];

    if (tid < NCAM * NPT) {
        const float fsx[7] = {0.f, 0.45f, -0.45f, 0.f, 0.f, 0.f, 0.f};
        const float fsy[7] = {0.f, 0.f, 0.f, 0.45f, -0.45f, 0.f, 0.f};
        const float fsz[7] = {0.f, 0.f, 0.f, 0.f, 0.f, 0.45f, -0.45f};
        int cam = tid / NPT, p = tid % NPT;
        const float* an = anchor + (size_t)ba * 8;
        float e0 = expf(an[3]), e1 = expf(an[4]), e2 = expf(an[5]);
        float k0 = fsx[p] * e0, k1 = fsy[p] * e1, k2 = fsz[p] * e2;
        float sn = an[6], cs = an[7];
        float X = cs * k0 - sn * k1 + an[0];
        float Y = sn * k0 + cs * k1 + an[1];
        float Z = k2 + an[2];
        const float* M = proj + (size_t)(b * NCAM + cam) * 16;
        float d0 = M[0] * X + M[1] * Y + M[2]  * Z + M[3];
        float d1 = M[4] * X + M[5] * Y + M[6]  * Z + M[7];
        float d2 = M[8] * X + M[9] * Y + M[10] * Z + M[11];
        float iz = 1.f / fmaxf(d2, 1e-5f);
        float x = d0 * iz / fmaxf(wh[(size_t)(b * NCAM + cam) * 2 + 0], 1e-5f);
        float y = d1 * iz / fmaxf(wh[(size_t)(b * NCAM + cam) * 2 + 1], 1e-5f);
        s_uv[tid][0] = x * 2.f - 1.f;
        s_uv[tid][1] = y * 2.f - 1.f;
    }
    __syncthreads();

    // softmax: warp wrp -> groups wrp*4..wrp*4+3
#pragma unroll
    for (int q = 0; q < 4; q++) {
        int gg = wrp * 4 + q;
        float mx = -INFINITY;
        for (int cc = lane; cc < 168; cc += 32) mx = fmaxf(mx, s_w[cc * 8 + gg]);
#pragma unroll
        for (int o = 16; o; o >>= 1) mx = fmaxf(mx, __shfl_xor_sync(0xffffffffu, mx, o));
        float sum = 0.f;
        for (int cc = lane; cc < 168; cc += 32) {
            float e = expf(s_w[cc * 8 + gg] - mx);
            s_w[cc * 8 + gg] = e;
            sum += e;
        }
#pragma unroll
        for (int o = 16; o; o >>= 1) sum += __shfl_xor_sync(0xffffffffu, sum, o);
        float inv = 1.f / sum;
        for (int cc = lane; cc < 168; cc += 32) s_w[cc * 8 + gg] *= inv;
    }

    // descriptors (168 over 64 threads, 3 iterations) + compaction
    const int Hl[4]  = {64, 32, 16, 8};
    const int Wl[4]  = {176, 88, 44, 22};
    const int HWl[4] = {HW0, HW1, HW2, HW3};
    const int PBl[4] = {PB0, PB1, PB2, PB3};
    int4   dA3[3];
    float4 dW3[3];
    unsigned bal3[3];
    int flags = 0;
#pragma unroll
    for (int it = 0; it < 3; it++) {
        int d = it * 64 + tid;
        int flag = 0;
        if (d < NDESC) {
            int cam = d / (NPT * NLVL);
            int r   = d - cam * (NPT * NLVL);
            int p   = r >> 2;
            int lvl = r & 3;
            float u = s_uv[cam * NPT + p][0];
            float v = s_uv[cam * NPT + p][1];
            const int H = Hl[lvl], W = Wl[lvl];
            float gx = (u + 1.f) * (W * 0.5f) - 0.5f;
            float gy = (v + 1.f) * (H * 0.5f) - 0.5f;
            float x0f = floorf(gx), y0f = floorf(gy);
            float wx1 = gx - x0f, wy1 = gy - y0f;
            bool vx0 = (x0f >= 0.f)       && (x0f <= (float)(W - 1));
            bool vx1 = (x0f + 1.f >= 0.f) && (x0f + 1.f <= (float)(W - 1));
            bool vy0 = (y0f >= 0.f)       && (y0f <= (float)(H - 1));
            bool vy1 = (y0f + 1.f >= 0.f) && (y0f + 1.f <= (float)(H - 1));
            flag = ((vx0 || vx1) && (vy0 || vy1)) ? 1 : 0;
            int x0 = (int)fminf(fmaxf(x0f, 0.f),       (float)(W - 1));
            int x1 = (int)fminf(fmaxf(x0f + 1.f, 0.f), (float)(W - 1));
            int y0 = (int)fminf(fmaxf(y0f, 0.f),       (float)(H - 1));
            int y1 = (int)fminf(fmaxf(y0f + 1.f, 0.f), (float)(H - 1));
            dA3[it].x = PBl[lvl] + (b * NCAM + cam) * HWl[lvl] + y0 * W + x0;
            dA3[it].y = (x1 - x0) * 256;
            dA3[it].z = (y1 - y0) * W * 256;
            dA3[it].w = ((cam * NLVL + lvl) * NPT + p) * NGRP;
            dW3[it].x = (vx0 && vy0) ? (1.f - wx1) * (1.f - wy1) : 0.f;
            dW3[it].y = (vx1 && vy0) ? wx1 * (1.f - wy1)         : 0.f;
            dW3[it].z = (vx0 && vy1) ? (1.f - wx1) * wy1         : 0.f;
            dW3[it].w = (vx1 && vy1) ? wx1 * wy1                 : 0.f;
        }
        bal3[it] = __ballot_sync(0xffffffffu, flag);
        flags |= flag << it;
        if (lane == 0) s_cnt[it * 2 + wrp] = __popc(bal3[it]);
    }
    __syncthreads();

    int pfx[6];
    {
        int run = 0;
#pragma unroll
        for (int i = 0; i < 6; i++) { pfx[i] = run; run += s_cnt[i]; }
    }
    int cnt = pfx[5] + s_cnt[5];
#pragma unroll
    for (int it = 0; it < 3; it++) {
        if ((flags >> it) & 1) {
            int pos = pfx[it * 2 + wrp] + __popc(bal3[it] & ((1u << lane) - 1u));
            s_dA[pos] = dA3[it];
            s_dW[pos] = dW3[it];
        }
    }
    __syncthreads();

    // gather + fuse: lane handles channels lane*8..lane*8+7 (one group);
    // warp wrp takes descriptors i = wrp, wrp+2, ...
    const int g = lane >> 2;                   // (lane*8)/32
    const __half* chan = g_nhwc + lane * 8;
    float a[8];
#pragma unroll
    for (int q = 0; q < 8; q++) a[q] = 0.f;

    for (int i = wrp; i < cnt; i += 2) {
        int4 D = s_dA[i];
        float4 wt = s_dW[i];
        const __half* bp = chan + (((size_t)D.x) << 8);
        uint4 r00 = *(const uint4*)(bp);
        uint4 r01 = *(const uint4*)(bp + D.y);
        uint4 r10 = *(const uint4*)(bp + D.z);
        uint4 r11 = *(const uint4*)(bp + D.z + D.y);
        float wf = s_w[D.w + g];
        const unsigned* p00 = &r00.x;
        const unsigned* p01 = &r01.x;
        const unsigned* p10 = &r10.x;
        const unsigned* p11 = &r11.x;
#pragma unroll
        for (int q = 0; q < 4; q++) {
            float2 v00 = __half22float2(*(const __half2*)&p00[q]);
            float2 v01 = __half22float2(*(const __half2*)&p01[q]);
            float2 v10 = __half22float2(*(const __half2*)&p10[q]);
            float2 v11 = __half22float2(*(const __half2*)&p11[q]);
            float sx = fmaf(wt.x, v00.x, fmaf(wt.y, v01.x, fmaf(wt.z, v10.x, wt.w * v11.x)));
            float sy = fmaf(wt.x, v00.y, fmaf(wt.y, v01.y, fmaf(wt.z, v10.y, wt.w * v11.y)));
            a[q * 2 + 0] = fmaf(sx, wf, a[q * 2 + 0]);
            a[q * 2 + 1] = fmaf(sy, wf, a[q * 2 + 1]);
        }
    }
#pragma unroll
    for (int q = 0; q < 8; q++) s_acc[wrp][lane * 8 + q] = a[q];
    __syncthreads();

    // combine warps' partials, store fp16 row-major
    {
        int c = tid * 4;
        float o0 = s_acc[0][c + 0] + s_acc[1][c + 0];
        float o1 = s_acc[0][c + 1] + s_acc[1][c + 1];
        float o2 = s_acc[0][c + 2] + s_acc[1][c + 2];
        float o3 = s_acc[0][c + 3] + s_acc[1][c + 3];
        __half2* fp = (__half2*)(g_fusedH + (size_t)ba * EDD + c);
        fp[0] = __floats2half2_rn(o0, o1);
        fp[1] = __floats2half2_rn(o2, o3);
    }
}

// =====================================================================
// Out-projection wmma with in-block split-K (8 warps: 2m x 2n x 2k)
// =====================================================================
__global__ void __launch_bounds__(256) outproj_wmma(
    const float* __restrict__ bias, float* __restrict__ out)
{
    __shared__ __align__(16) float sm[2][64][72];
    const int bx = blockIdx.x;                 // n tile (4)
    const int by = blockIdx.y;                 // m tile (30)
    const int tid = threadIdx.x;
    const int wid = tid >> 5;
    const int wk  = wid >> 2;                  // k half
    const int wm  = (wid >> 1) & 1;
    const int wn  = wid & 1;
    const int m0 = by * 64 + wm * 32;
    const int n0 = bx * 64 + wn * 32;

    wmma::fragment<wmma::accumulator, 16, 16, 16, float> cf[2][2];
#pragma unroll
    for (int i = 0; i < 2; i++)
#pragma unroll
        for (int j = 0; j < 2; j++) wmma::fill_fragment(cf[i][j], 0.f);

    for (int k0 = wk * 128; k0 < wk * 128 + 128; k0 += 16) {
        wmma::fragment<wmma::matrix_a, 16, 16, 16, __half, wmma::row_major> af[2];
        wmma::fragment<wmma::matrix_b, 16, 16, 16, __half, wmma::col_major> bf[2];
#pragma unroll
        for (int i = 0; i < 2; i++)
            wmma::load_matrix_sync(af[i], g_fusedH + (size_t)(m0 + i * 16) * EDD + k0, EDD);
#pragma unroll
        for (int j = 0; j < 2; j++)
            wmma::load_matrix_sync(bf[j], g_woutH + (size_t)(n0 + j * 16) * EDD + k0, EDD);
#pragma unroll
        for (int i = 0; i < 2; i++)
#pragma unroll
            for (int j = 0; j < 2; j++)
                wmma::mma_sync(cf[i][j], af[i], bf[j], cf[i][j]);
    }
#pragma unroll
    for (int i = 0; i < 2; i++)
#pragma unroll
        for (int j = 0; j < 2; j++)
            wmma::store_matrix_sync(&sm[wk][wm * 32 + i * 16][wn * 32 + j * 16],
                                    cf[i][j], 72, wmma::mem_row_major);
    __syncthreads();

    // epilogue: sum k-halves + bias, write rows m < NBA
    const int c = (tid & 15) * 4;
    float4 bb = *(const float4*)(bias + bx * 64 + c);
    for (int r = (tid >> 4); r < 64; r += 16) {
        int m = by * 64 + r;
        if (m >= NBA) break;
        float4 o;
        o.x = sm[0][r][c + 0] + sm[1][r][c + 0] + bb.x;
        o.y = sm[0][r][c + 1] + sm[1][r][c + 1] + bb.y;
        o.z = sm[0][r][c + 2] + sm[1][r][c + 2] + bb.z;
        o.w = sm[0][r][c + 3] + sm[1][r][c + 3] + bb.w;
        *(float4*)(out + (size_t)m * EDD + bx * 64 + c) = o;
    }
}

// =====================================================================
// launch
// =====================================================================
extern "C" void kernel_launch(void* const* d_in, const int* in_sizes, int n_in,
                              void* d_out, int out_size)
{
    const float* inst   = (const float*)d_in[0];
    const float* anchor = (const float*)d_in[1];
    const float* emb    = (const float*)d_in[2];
    const float* f0     = (const float*)d_in[3];
    const float* f1     = (const float*)d_in[4];
    const float* f2     = (const float*)d_in[5];
    const float* f3     = (const float*)d_in[6];
    const float* proj   = (const float*)d_in[7];
    const float* wh     = (const float*)d_in[8];
    const float* w_fc   = (const float*)d_in[9];
    const float* b_fc   = (const float*)d_in[10];
    const float* w_out  = (const float*)d_in[11];
    const float* b_out  = (const float*)d_in[12];
    float* out = (float*)d_out;

    mega_kernel<<<GEMM_BLKS + CVTOT + WOUT_BLKS, 256>>>(
        inst, emb, w_fc, w_out, f0, f1, f2, f3);
    agg_kernel<<<NBA, 64>>>(anchor, proj, wh, b_fc);
    outproj_wmma<<<dim3(EDD / 64, MPAD / 64), 256>>>(b_out, out);
}

// round 10
// speedup vs baseline: 2.0543x; 1.0351x over previous
#include <cuda_runtime.h>
#include <cuda_fp16.h>
#include <mma.h>
#include <math.h>

using namespace nvcuda;

// ----- problem constants -----
#define BB    2
#define AA    900
#define EDD   256
#define NGRP  8
#define NCAM  6
#define NLVL  4
#define NPT   7
#define NW    1344            // NGRP*NCAM*NLVL*NPT
#define NBA   (BB*AA)         // 1800
#define MPAD  1920
#define NDESC (NCAM*NPT*NLVL) // 168
#define NBC   (BB*NCAM)       // 12

// level geometry
#define HW0 11264
#define HW1 2816
#define HW2 704
#define HW3 176
#define PB0 0
#define PB1 (NBC*HW0)
#define PB2 (PB1 + NBC*HW1)
#define PB3 (PB2 + NBC*HW2)
#define NPIX (PB3 + NBC*HW3)           // 179520

// conversion blocks
#define CT0 176
#define CT1 44
#define CT2 11
#define CT3 3
#define CV0 (NBC*CT0*4)
#define CV1 (NBC*CT1*4)
#define CV2 (NBC*CT2*4)
#define CV3 (NBC*CT3*4)
#define CVTOT (CV0+CV1+CV2+CV3)        // 11232

#define GEMM_BLKS ((NW/64) * (MPAD/128))   // 315
#define WOUT_BLKS 64

// ----- scratch (allocation-free: device globals; zero-initialized) -----
__device__ __align__(16) __half g_woutH[EDD * EDD];
__device__ __align__(16) float  g_w[MPAD * NW];
__device__ __align__(16) __half g_fusedH[MPAD * EDD];
__device__ __align__(16) __half g_nhwc[(size_t)NPIX * EDD];

// =====================================================================
// FC GEMM kernel: g_w[MPAD][NW] = (inst+emb) @ w_fc^T (fp16 wmma),
// plus w_out fp32->fp16 conversion in tail blocks.
// =====================================================================
__global__ void __launch_bounds__(256) fc_gemm_kernel(
    const float* __restrict__ inst, const float* __restrict__ emb,
    const float* __restrict__ w_fc, const float* __restrict__ w_out)
{
    __shared__ __align__(16) __half sA[128 * 32];
    __shared__ __align__(16) __half sB[64 * 32];
    const int tid = threadIdx.x;

    if (blockIdx.x >= GEMM_BLKS) {
        // w_out fp32 -> fp16
        int j = (blockIdx.x - GEMM_BLKS) * 256 + tid;   // float4 idx
        float4 v = *(const float4*)(w_out + (size_t)j * 4);
        __half2 h0 = __floats2half2_rn(v.x, v.y);
        __half2 h1 = __floats2half2_rn(v.z, v.w);
        uint2 o;
        o.x = *(unsigned*)&h0;
        o.y = *(unsigned*)&h1;
        *(uint2*)(g_woutH + (size_t)j * 4) = o;
        return;
    }

    const int gx = blockIdx.x % (NW / 64);
    const int gy = blockIdx.x / (NW / 64);
    const int bm0 = gy * 128;
    const int bn0 = gx * 64;
    const int wid = tid >> 5;
    const int wm  = wid & 3;
    const int wn  = wid >> 2;
    const int m0 = wm * 32;
    const int n0 = wn * 32;

    wmma::fragment<wmma::accumulator, 16, 16, 16, float> cf[2][2];
#pragma unroll
    for (int i = 0; i < 2; i++)
#pragma unroll
        for (int j = 0; j < 2; j++) wmma::fill_fragment(cf[i][j], 0.f);

    for (int kt = 0; kt < 256; kt += 32) {
#pragma unroll
        for (int s = 0; s < 4; s++) {
            int id = tid + s * 256;
            int row = id >> 3, q = id & 7;
            int m = bm0 + row;
            float4 v = make_float4(0.f, 0.f, 0.f, 0.f);
            if (m < NBA) {
                v = *(const float4*)(inst + (size_t)m * 256 + kt + q * 4);
                float4 w = *(const float4*)(emb + (size_t)m * 256 + kt + q * 4);
                v.x += w.x; v.y += w.y; v.z += w.z; v.w += w.w;
            }
            __half2* d = (__half2*)&sA[row * 32 + q * 4];
            d[0] = __floats2half2_rn(v.x, v.y);
            d[1] = __floats2half2_rn(v.z, v.w);
        }
#pragma unroll
        for (int s = 0; s < 2; s++) {
            int id = tid + s * 256;
            int row = id >> 3, q = id & 7;
            int n = bn0 + row;
            float4 v = *(const float4*)(w_fc + (size_t)n * 256 + kt + q * 4);
            __half2* d = (__half2*)&sB[row * 32 + q * 4];
            d[0] = __floats2half2_rn(v.x, v.y);
            d[1] = __floats2half2_rn(v.z, v.w);
        }
        __syncthreads();

#pragma unroll
        for (int kk = 0; kk < 2; kk++) {
            wmma::fragment<wmma::matrix_a, 16, 16, 16, __half, wmma::row_major> af[2];
            wmma::fragment<wmma::matrix_b, 16, 16, 16, __half, wmma::col_major> bf[2];
#pragma unroll
            for (int i = 0; i < 2; i++)
                wmma::load_matrix_sync(af[i], sA + (m0 + i * 16) * 32 + kk * 16, 32);
#pragma unroll
            for (int j = 0; j < 2; j++)
                wmma::load_matrix_sync(bf[j], sB + (n0 + j * 16) * 32 + kk * 16, 32);
#pragma unroll
            for (int i = 0; i < 2; i++)
#pragma unroll
                for (int j = 0; j < 2; j++)
                    wmma::mma_sync(cf[i][j], af[i], bf[j], cf[i][j]);
        }
        __syncthreads();
    }
#pragma unroll
    for (int i = 0; i < 2; i++)
#pragma unroll
        for (int j = 0; j < 2; j++)
            wmma::store_matrix_sync(g_w + (size_t)(bm0 + m0 + i * 16) * NW + bn0 + n0 + j * 16,
                                    cf[i][j], NW, wmma::mem_row_major);
}

// =====================================================================
// Conversion kernel (lean, high occupancy): NCHW fp32 -> NHWC fp16.
// 64ch x 64px tile per block, 256 threads.
// =====================================================================
__global__ void __launch_bounds__(256) conv_kernel(
    const float* __restrict__ f0, const float* __restrict__ f1,
    const float* __restrict__ f2, const float* __restrict__ f3)
{
    __shared__ float t[64][65];
    const int tid = threadIdx.x;

    int cb = blockIdx.x;
    const float* fin; int HWl, tilesHW, pbase;
    if (cb < CV0)               { fin = f0; HWl = HW0; tilesHW = CT0; pbase = PB0; }
    else if ((cb -= CV0) < CV1) { fin = f1; HWl = HW1; tilesHW = CT1; pbase = PB1; }
    else if ((cb -= CV1) < CV2) { fin = f2; HWl = HW2; tilesHW = CT2; pbase = PB2; }
    else       { cb -= CV2;       fin = f3; HWl = HW3; tilesHW = CT3; pbase = PB3; }
    const int nt  = tilesHW * 4;
    const int bc  = cb / nt;
    const int r   = cb % nt;
    const int hw0 = (r >> 2) * 64;
    const int c0  = (r & 3) * 64;

    const float* ip = fin + (size_t)bc * 256 * HWl;
#pragma unroll
    for (int s = 0; s < 4; s++) {
        int id = tid + s * 256;
        int row = id >> 4, q = id & 15;
        int hw = hw0 + q * 4;
        if (hw < HWl) {
            float4 v = __ldcs((const float4*)(ip + (size_t)(c0 + row) * HWl + hw));
            t[row][q * 4 + 0] = v.x;
            t[row][q * 4 + 1] = v.y;
            t[row][q * 4 + 2] = v.z;
            t[row][q * 4 + 3] = v.w;
        }
    }
    __syncthreads();
    __half* op = g_nhwc + ((size_t)(pbase + bc * HWl)) * 256;
#pragma unroll
    for (int s = 0; s < 4; s++) {
        int id = tid + s * 256;
        int px = id >> 4, qc = id & 15;
        int hw = hw0 + px;
        if (hw < HWl) {
            __half2 h0 = __floats2half2_rn(t[qc * 4 + 0][px], t[qc * 4 + 1][px]);
            __half2 h1 = __floats2half2_rn(t[qc * 4 + 2][px], t[qc * 4 + 3][px]);
            uint2 o;
            o.x = *(unsigned*)&h0;
            o.y = *(unsigned*)&h1;
            *(uint2*)(op + (size_t)hw * 256 + c0 + qc * 4) = o;
        }
    }
}

// =====================================================================
// Fused aggregation: 64 threads; each thread covers 8 channels (uint4
// gathers); the two warps split the descriptor list (evens/odds).
// =====================================================================
__global__ void __launch_bounds__(64) agg_kernel(
    const float* __restrict__ anchor, const float* __restrict__ proj,
    const float* __restrict__ wh, const float* __restrict__ b_fc)
{
    __shared__ float  s_w[NW];
    __shared__ float  s_uv[NCAM * NPT][2];
    __shared__ int4   s_dA[NDESC];
    __shared__ float4 s_dW[NDESC];
    __shared__ int    s_cnt[6];
    __shared__ float  s_acc[2][EDD];

    const int ba   = blockIdx.x;
    const int b    = ba / AA;
    const int tid  = threadIdx.x;
    const int wrp  = tid >> 5;
    const int lane = tid & 31;

    for (int i = tid; i < NW; i += 64) s_w[i] = g_w[(size_t)ba * NW + i] + b_fc[i];

    if (tid < NCAM * NPT) {
        const float fsx[7] = {0.f, 0.45f, -0.45f, 0.f, 0.f, 0.f, 0.f};
        const float fsy[7] = {0.f, 0.f, 0.f, 0.45f, -0.45f, 0.f, 0.f};
        const float fsz[7] = {0.f, 0.f, 0.f, 0.f, 0.f, 0.45f, -0.45f};
        int cam = tid / NPT, p = tid % NPT;
        const float* an = anchor + (size_t)ba * 8;
        float e0 = expf(an[3]), e1 = expf(an[4]), e2 = expf(an[5]);
        float k0 = fsx[p] * e0, k1 = fsy[p] * e1, k2 = fsz[p] * e2;
        float sn = an[6], cs = an[7];
        float X = cs * k0 - sn * k1 + an[0];
        float Y = sn * k0 + cs * k1 + an[1];
        float Z = k2 + an[2];
        const float* M = proj + (size_t)(b * NCAM + cam) * 16;
        float d0 = M[0] * X + M[1] * Y + M[2]  * Z + M[3];
        float d1 = M[4] * X + M[5] * Y + M[6]  * Z + M[7];
        float d2 = M[8] * X + M[9] * Y + M[10] * Z + M[11];
        float iz = 1.f / fmaxf(d2, 1e-5f);
        float x = d0 * iz / fmaxf(wh[(size_t)(b * NCAM + cam) * 2 + 0], 1e-5f);
        float y = d1 * iz / fmaxf(wh[(size_t)(b * NCAM + cam) * 2 + 1], 1e-5f);
        s_uv[tid][0] = x * 2.f - 1.f;
        s_uv[tid][1] = y * 2.f - 1.f;
    }
    __syncthreads();

#pragma unroll
    for (int q = 0; q < 4; q++) {
        int gg = wrp * 4 + q;
        float mx = -INFINITY;
        for (int cc = lane; cc < 168; cc += 32) mx = fmaxf(mx, s_w[cc * 8 + gg]);
#pragma unroll
        for (int o = 16; o; o >>= 1) mx = fmaxf(mx, __shfl_xor_sync(0xffffffffu, mx, o));
        float sum = 0.f;
        for (int cc = lane; cc < 168; cc += 32) {
            float e = expf(s_w[cc * 8 + gg] - mx);
            s_w[cc * 8 + gg] = e;
            sum += e;
        }
#pragma unroll
        for (int o = 16; o; o >>= 1) sum += __shfl_xor_sync(0xffffffffu, sum, o);
        float inv = 1.f / sum;
        for (int cc = lane; cc < 168; cc += 32) s_w[cc * 8 + gg] *= inv;
    }

    const int Hl[4]  = {64, 32, 16, 8};
    const int Wl[4]  = {176, 88, 44, 22};
    const int HWl[4] = {HW0, HW1, HW2, HW3};
    const int PBl[4] = {PB0, PB1, PB2, PB3};
    int4   dA3[3];
    float4 dW3[3];
    unsigned bal3[3];
    int flags = 0;
#pragma unroll
    for (int it = 0; it < 3; it++) {
        int d = it * 64 + tid;
        int flag = 0;
        if (d < NDESC) {
            int cam = d / (NPT * NLVL);
            int r   = d - cam * (NPT * NLVL);
            int p   = r >> 2;
            int lvl = r & 3;
            float u = s_uv[cam * NPT + p][0];
            float v = s_uv[cam * NPT + p][1];
            const int H = Hl[lvl], W = Wl[lvl];
            float gx = (u + 1.f) * (W * 0.5f) - 0.5f;
            float gy = (v + 1.f) * (H * 0.5f) - 0.5f;
            float x0f = floorf(gx), y0f = floorf(gy);
            float wx1 = gx - x0f, wy1 = gy - y0f;
            bool vx0 = (x0f >= 0.f)       && (x0f <= (float)(W - 1));
            bool vx1 = (x0f + 1.f >= 0.f) && (x0f + 1.f <= (float)(W - 1));
            bool vy0 = (y0f >= 0.f)       && (y0f <= (float)(H - 1));
            bool vy1 = (y0f + 1.f >= 0.f) && (y0f + 1.f <= (float)(H - 1));
            flag = ((vx0 || vx1) && (vy0 || vy1)) ? 1 : 0;
            int x0 = (int)fminf(fmaxf(x0f, 0.f),       (float)(W - 1));
            int x1 = (int)fminf(fmaxf(x0f + 1.f, 0.f), (float)(W - 1));
            int y0 = (int)fminf(fmaxf(y0f, 0.f),       (float)(H - 1));
            int y1 = (int)fminf(fmaxf(y0f + 1.f, 0.f), (float)(H - 1));
            dA3[it].x = PBl[lvl] + (b * NCAM + cam) * HWl[lvl] + y0 * W + x0;
            dA3[it].y = (x1 - x0) * 256;
            dA3[it].z = (y1 - y0) * W * 256;
            dA3[it].w = ((cam * NLVL + lvl) * NPT + p) * NGRP;
            dW3[it].x = (vx0 && vy0) ? (1.f - wx1) * (1.f - wy1) : 0.f;
            dW3[it].y = (vx1 && vy0) ? wx1 * (1.f - wy1)         : 0.f;
            dW3[it].z = (vx0 && vy1) ? (1.f - wx1) * wy1         : 0.f;
            dW3[it].w = (vx1 && vy1) ? wx1 * wy1                 : 0.f;
        }
        bal3[it] = __ballot_sync(0xffffffffu, flag);
        flags |= flag << it;
        if (lane == 0) s_cnt[it * 2 + wrp] = __popc(bal3[it]);
    }
    __syncthreads();

    int pfx[6];
    {
        int run = 0;
#pragma unroll
        for (int i = 0; i < 6; i++) { pfx[i] = run; run += s_cnt[i]; }
    }
    int cnt = pfx[5] + s_cnt[5];
#pragma unroll
    for (int it = 0; it < 3; it++) {
        if ((flags >> it) & 1) {
            int pos = pfx[it * 2 + wrp] + __popc(bal3[it] & ((1u << lane) - 1u));
            s_dA[pos] = dA3[it];
            s_dW[pos] = dW3[it];
        }
    }
    __syncthreads();

    const int g = lane >> 2;
    const __half* chan = g_nhwc + lane * 8;
    float a[8];
#pragma unroll
    for (int q = 0; q < 8; q++) a[q] = 0.f;

    for (int i = wrp; i < cnt; i += 2) {
        int4 D = s_dA[i];
        float4 wt = s_dW[i];
        const __half* bp = chan + (((size_t)D.x) << 8);
        uint4 r00 = *(const uint4*)(bp);
        uint4 r01 = *(const uint4*)(bp + D.y);
        uint4 r10 = *(const uint4*)(bp + D.z);
        uint4 r11 = *(const uint4*)(bp + D.z + D.y);
        float wf = s_w[D.w + g];
        const unsigned* p00 = &r00.x;
        const unsigned* p01 = &r01.x;
        const unsigned* p10 = &r10.x;
        const unsigned* p11 = &r11.x;
#pragma unroll
        for (int q = 0; q < 4; q++) {
            float2 v00 = __half22float2(*(const __half2*)&p00[q]);
            float2 v01 = __half22float2(*(const __half2*)&p01[q]);
            float2 v10 = __half22float2(*(const __half2*)&p10[q]);
            float2 v11 = __half22float2(*(const __half2*)&p11[q]);
            float sx = fmaf(wt.x, v00.x, fmaf(wt.y, v01.x, fmaf(wt.z, v10.x, wt.w * v11.x)));
            float sy = fmaf(wt.x, v00.y, fmaf(wt.y, v01.y, fmaf(wt.z, v10.y, wt.w * v11.y)));
            a[q * 2 + 0] = fmaf(sx, wf, a[q * 2 + 0]);
            a[q * 2 + 1] = fmaf(sy, wf, a[q * 2 + 1]);
        }
    }
#pragma unroll
    for (int q = 0; q < 8; q++) s_acc[wrp][lane * 8 + q] = a[q];
    __syncthreads();

    {
        int c = tid * 4;
        float o0 = s_acc[0][c + 0] + s_acc[1][c + 0];
        float o1 = s_acc[0][c + 1] + s_acc[1][c + 1];
        float o2 = s_acc[0][c + 2] + s_acc[1][c + 2];
        float o3 = s_acc[0][c + 3] + s_acc[1][c + 3];
        __half2* fp = (__half2*)(g_fusedH + (size_t)ba * EDD + c);
        fp[0] = __floats2half2_rn(o0, o1);
        fp[1] = __floats2half2_rn(o2, o3);
    }
}

// =====================================================================
// Out-projection wmma: 32m x 64n tiles, 8 warps (2n x 4k split-K).
// =====================================================================
__global__ void __launch_bounds__(256) outproj_wmma(
    const float* __restrict__ bias, float* __restrict__ out)
{
    __shared__ __align__(16) float sm[4][32][72];
    const int bx = blockIdx.x;                 // n tile (4)
    const int by = blockIdx.y;                 // m tile (60)
    const int tid = threadIdx.x;
    const int wid = tid >> 5;
    const int wk  = wid >> 1;                  // 0..3
    const int wn  = wid & 1;
    const int m0 = by * 32;
    const int n0 = bx * 64 + wn * 32;

    wmma::fragment<wmma::accumulator, 16, 16, 16, float> cf[2][2];
#pragma unroll
    for (int i = 0; i < 2; i++)
#pragma unroll
        for (int j = 0; j < 2; j++) wmma::fill_fragment(cf[i][j], 0.f);

    for (int k0 = wk * 64; k0 < wk * 64 + 64; k0 += 16) {
        wmma::fragment<wmma::matrix_a, 16, 16, 16, __half, wmma::row_major> af[2];
        wmma::fragment<wmma::matrix_b, 16, 16, 16, __half, wmma::col_major> bf[2];
#pragma unroll
        for (int i = 0; i < 2; i++)
            wmma::load_matrix_sync(af[i], g_fusedH + (size_t)(m0 + i * 16) * EDD + k0, EDD);
#pragma unroll
        for (int j = 0; j < 2; j++)
            wmma::load_matrix_sync(bf[j], g_woutH + (size_t)(n0 + j * 16) * EDD + k0, EDD);
#pragma unroll
        for (int i = 0; i < 2; i++)
#pragma unroll
            for (int j = 0; j < 2; j++)
                wmma::mma_sync(cf[i][j], af[i], bf[j], cf[i][j]);
    }
#pragma unroll
    for (int i = 0; i < 2; i++)
#pragma unroll
        for (int j = 0; j < 2; j++)
            wmma::store_matrix_sync(&sm[wk][i * 16][wn * 32 + j * 16],
                                    cf[i][j], 72, wmma::mem_row_major);
    __syncthreads();

    const int c = (tid & 15) * 4;
    float4 bb = *(const float4*)(bias + bx * 64 + c);
    for (int r = (tid >> 4); r < 32; r += 16) {
        int m = by * 32 + r;
        if (m >= NBA) break;
        float4 o;
        o.x = sm[0][r][c + 0] + sm[1][r][c + 0] + sm[2][r][c + 0] + sm[3][r][c + 0] + bb.x;
        o.y = sm[0][r][c + 1] + sm[1][r][c + 1] + sm[2][r][c + 1] + sm[3][r][c + 1] + bb.y;
        o.z = sm[0][r][c + 2] + sm[1][r][c + 2] + sm[2][r][c + 2] + sm[3][r][c + 2] + bb.z;
        o.w = sm[0][r][c + 3] + sm[1][r][c + 3] + sm[2][r][c + 3] + sm[3][r][c + 3] + bb.w;
        *(float4*)(out + (size_t)m * EDD + bx * 64 + c) = o;
    }
}

// =====================================================================
// launch
// =====================================================================
extern "C" void kernel_launch(void* const* d_in, const int* in_sizes, int n_in,
                              void* d_out, int out_size)
{
    const float* inst   = (const float*)d_in[0];
    const float* anchor = (const float*)d_in[1];
    const float* emb    = (const float*)d_in[2];
    const float* f0     = (const float*)d_in[3];
    const float* f1     = (const float*)d_in[4];
    const float* f2     = (const float*)d_in[5];
    const float* f3     = (const float*)d_in[6];
    const float* proj   = (const float*)d_in[7];
    const float* wh     = (const float*)d_in[8];
    const float* w_fc   = (const float*)d_in[9];
    const float* b_fc   = (const float*)d_in[10];
    const float* w_out  = (const float*)d_in[11];
    const float* b_out  = (const float*)d_in[12];
    float* out = (float*)d_out;

    fc_gemm_kernel<<<GEMM_BLKS + WOUT_BLKS, 256>>>(inst, emb, w_fc, w_out);
    conv_kernel<<<CVTOT, 256>>>(f0, f1, f2, f3);
    agg_kernel<<<NBA, 64>>>(anchor, proj, wh, b_fc);
    outproj_wmma<<<dim3(EDD / 64, MPAD / 32), 256>>>(b_out, out);
}